// round 12
// baseline (speedup 1.0000x reference)
#include <cuda_runtime.h>
#include <cuda_fp16.h>
#include <cstdint>
#include <cstddef>

#define BATCH 2
#define SEQ   2048
#define DIM   1024
#define NHEAD 16
#define HD    64
// SCALE * log2(e): logits kept in base-2 domain (folded into Q at QKV epilogue)
#define SC2   0.18033688011112042f

#define NSLOTS 296   // 148 SMs x 2 CTAs/SM

// ---------------------------------------------------------------------------
// Scratch (allocation-free rule: __device__ globals) — fp16 scheme
// ---------------------------------------------------------------------------
__device__ __half g_xhi[(size_t)BATCH * SEQ * DIM];
__device__ __half g_xlo[(size_t)BATCH * SEQ * DIM];
__device__ __half g_qh [(size_t)BATCH * SEQ * 3 * DIM];   // qkv hi
__device__ __half g_ql [(size_t)BATCH * SEQ * 3 * DIM];   // qkv lo (only Q read)
__device__ __half g_ahi[(size_t)BATCH * SEQ * DIM];       // attn hi
__device__ __half g_alo[(size_t)BATCH * SEQ * DIM];       // attn lo
__device__ __half g_wqh[(size_t)3 * DIM * DIM];           // [3072,1024] K-major, hi only
__device__ __half g_wph[(size_t)DIM * DIM];               // [1024,1024] K-major, hi only

// ---------------------------------------------------------------------------
// Portable PTX helpers
// ---------------------------------------------------------------------------
__device__ __forceinline__ uint32_t smem_u32(const void* p) {
    uint32_t a;
    asm("{ .reg .u64 t; cvta.to.shared.u64 t, %1; cvt.u32.u64 %0, t; }" : "=r"(a) : "l"(p));
    return a;
}
#define CPA16(dst, src) \
    asm volatile("cp.async.cg.shared.global [%0], [%1], 16;" :: "r"(dst), "l"(src) : "memory")
#define CP_COMMIT() asm volatile("cp.async.commit_group;" ::: "memory")
#define CP_WAIT0()  asm volatile("cp.async.wait_group 0;" ::: "memory")
#define CP_WAIT1()  asm volatile("cp.async.wait_group 1;" ::: "memory")

#define LDSM_X4(r, addr) \
    asm volatile("ldmatrix.sync.aligned.m8n8.x4.shared.b16 {%0,%1,%2,%3}, [%4];" \
        : "=r"((r)[0]), "=r"((r)[1]), "=r"((r)[2]), "=r"((r)[3]) : "r"(addr))
#define LDSM_X4T(r, addr) \
    asm volatile("ldmatrix.sync.aligned.m8n8.x4.trans.shared.b16 {%0,%1,%2,%3}, [%4];" \
        : "=r"((r)[0]), "=r"((r)[1]), "=r"((r)[2]), "=r"((r)[3]) : "r"(addr))

// fp16 HMMA, fp32 accumulate
#define MMA16816(c, a, b) \
    asm volatile("mma.sync.aligned.m16n8k16.row.col.f32.f16.f16.f32 " \
        "{%0,%1,%2,%3}, {%4,%5,%6,%7}, {%8,%9}, {%0,%1,%2,%3};" \
        : "+f"((c)[0]), "+f"((c)[1]), "+f"((c)[2]), "+f"((c)[3]) \
        : "r"((a)[0]), "r"((a)[1]), "r"((a)[2]), "r"((a)[3]), "r"((b)[0]), "r"((b)[1]))

#define SWZ64(off)  ((off) ^ (((off) >> 3) & 0x30))
#define SWZ128(off) ((off) ^ (((off) >> 3) & 0x70))

__device__ __forceinline__ float ex2f(float x) {
    float y; asm("ex2.approx.ftz.f32 %0, %1;" : "=f"(y) : "f"(x)); return y;
}
__device__ __forceinline__ uint32_t pack_hf2(float a, float b) {
    __half2 h = __floats2half2_rn(a, b);
    return *(uint32_t*)&h;
}

// ---------------------------------------------------------------------------
// Preprocessing
// ---------------------------------------------------------------------------
__global__ __launch_bounds__(256) void split_kernel(
    const float* __restrict__ X, __half* __restrict__ hi,
    __half* __restrict__ lo, int n4)
{
    int i = blockIdx.x * blockDim.x + threadIdx.x;
    if (i >= n4) return;
    float4 v = ((const float4*)X)[i];
    __half h[4], l[4];
    float f[4] = {v.x, v.y, v.z, v.w};
    #pragma unroll
    for (int j = 0; j < 4; j++) {
        h[j] = __float2half_rn(f[j]);
        l[j] = __float2half_rn(f[j] - __half2float(h[j]));
    }
    ((uint2*)hi)[i] = *(uint2*)h;
    ((uint2*)lo)[i] = *(uint2*)l;
}

// W [K, N] fp32 -> T [N, K] fp16 hi only (transpose + quantize)
__global__ __launch_bounds__(256) void transpose_h(
    const float* __restrict__ W, __half* __restrict__ Th, int K, int N)
{
    __shared__ float tile[32][33];
    int tx = threadIdx.x & 31, ty = threadIdx.x >> 5;
    int k0 = blockIdx.y * 32, n0 = blockIdx.x * 32;
    #pragma unroll
    for (int i = 0; i < 32; i += 8)
        tile[ty + i][tx] = W[(size_t)(k0 + ty + i) * N + n0 + tx];
    __syncthreads();
    #pragma unroll
    for (int i = 0; i < 32; i += 8) {
        float v = tile[tx][ty + i];
        Th[(size_t)(n0 + ty + i) * K + k0 + tx] = __float2half_rn(v);
    }
}

// ---------------------------------------------------------------------------
// HMMA fp16 2-product GEMM (persistent CTAs): C = (Ahi+Alo)[M,K] @ Bh[N,K]^T
// CTA tile 128x128, BK=32, 3-stage cp.async, 2 CTAs/SM, tile loop per CTA.
// Stage (24KB): Ahi[0,8K) Alo[8K,16K) Bh[16K,24K)
// ---------------------------------------------------------------------------
#define GST 24576
#define GSMEM_TOTAL (3 * GST)

#define LOAD_STAGE(sidx, kc) do {                                              \
    uint32_t sb = sbase + (uint32_t)(sidx) * GST;                              \
    _Pragma("unroll")                                                          \
    for (int t_ = 0; t_ < 2; ++t_) {                                           \
        int v_ = tid + t_ * 256;                                               \
        int row_ = v_ >> 2, cb_ = v_ & 3;                                      \
        uint32_t sw_ = SWZ64((uint32_t)(row_ * 64 + cb_ * 16));                \
        size_t gA_ = (size_t)(rowBase + row_) * K + (kc) + cb_ * 8;            \
        size_t gB_ = (size_t)(colBase + row_) * K + (kc) + cb_ * 8;            \
        CPA16(sb + sw_,         (const char*)(Ahi + gA_));                     \
        CPA16(sb + 8192  + sw_, (const char*)(Alo + gA_));                     \
        CPA16(sb + 16384 + sw_, (const char*)(Bh + gB_));                      \
    }                                                                          \
} while (0)

template <bool SPLIT>
__global__ __launch_bounds__(256, 2) void gemm_mma(
    const __half* __restrict__ Ahi, const __half* __restrict__ Alo,
    const __half* __restrict__ Bh,
    float* __restrict__ C, __half* __restrict__ Chi,
    __half* __restrict__ Clo, int M, int N, int K)
{
    extern __shared__ char smem[];
    const uint32_t sbase = smem_u32(smem);
    const int tid  = threadIdx.x;
    const int lane = tid & 31;
    const int wid  = tid >> 5;
    const int wm = (wid & 3) * 32;
    const int wn = (wid >> 2) * 64;

    const int mi = lane >> 3;
    const uint32_t a_off = (uint32_t)((((mi & 1) * 8 + (lane & 7)) * 64) + (mi >> 1) * 16);
    const uint32_t b_off = (uint32_t)((((mi >> 1) * 8 + (lane & 7)) * 64) + (mi & 1) * 16);

    const int ntx = N / 128;
    const int ntiles = ntx * (M / 128);
    const int nk = K / 32;                 // 32

    for (int tIdx = blockIdx.x; tIdx < ntiles; tIdx += gridDim.x) {
        const int rowBase = (tIdx / ntx) * 128;
        const int colBase = (tIdx % ntx) * 128;

        float acc[2][8][4];
        #pragma unroll
        for (int i = 0; i < 2; i++)
            #pragma unroll
            for (int j = 0; j < 8; j++)
                #pragma unroll
                for (int q = 0; q < 4; q++) acc[i][j][q] = 0.f;

        __syncthreads();   // previous tile's smem reads complete before refill
        LOAD_STAGE(0, 0);  CP_COMMIT();
        LOAD_STAGE(1, 32); CP_COMMIT();

        int sidx = 0;
        for (int c = 0; c < nk; ++c) {
            if (c + 1 < nk) { CP_WAIT1(); } else { CP_WAIT0(); }
            __syncthreads();
            if (c + 2 < nk) {
                int ns = sidx + 2; if (ns >= 3) ns -= 3;
                LOAD_STAGE(ns, (c + 2) * 32);
                CP_COMMIT();
            }

            const uint32_t st = sbase + (uint32_t)sidx * GST;

            // hoist all A fragments for this chunk (both kb halves)
            uint32_t Ah[2][2][4], Al[2][2][4];
            #pragma unroll
            for (int kb2 = 0; kb2 < 2; kb2++)
                #pragma unroll
                for (int i = 0; i < 2; i++) {
                    uint32_t off = (uint32_t)((wm + i * 16) * 64 + kb2 * 32) + a_off;
                    LDSM_X4(Ah[kb2][i], st + SWZ64(off));
                    LDSM_X4(Al[kb2][i], st + 8192 + SWZ64(off));
                }

            // B fragments double-buffered across the flattened (kb, jp) loop
            uint32_t Bf[2][4];
            {
                uint32_t off = (uint32_t)(wn * 64) + b_off;   // kb=0, jp=0
                LDSM_X4(Bf[0], st + 16384 + SWZ64(off));
            }
            int bb = 0;
            #pragma unroll
            for (int it = 0; it < 8; it++) {            // it = kb*4 + jp
                const int kb = it >> 2, jp = it & 3;
                if (it + 1 < 8) {
                    const int nkb = (it + 1) >> 2, njp = (it + 1) & 3;
                    uint32_t off = (uint32_t)((wn + njp * 16) * 64 + nkb * 32) + b_off;
                    LDSM_X4(Bf[bb ^ 1], st + 16384 + SWZ64(off));
                }
                // 2-product: A-side exact, B-side fp16
                #pragma unroll
                for (int i = 0; i < 2; i++)
                    #pragma unroll
                    for (int jj = 0; jj < 2; jj++)
                        MMA16816(acc[i][jp * 2 + jj], Ah[kb][i], (&Bf[bb][jj * 2]));
                #pragma unroll
                for (int i = 0; i < 2; i++)
                    #pragma unroll
                    for (int jj = 0; jj < 2; jj++)
                        MMA16816(acc[i][jp * 2 + jj], Al[kb][i], (&Bf[bb][jj * 2]));
                bb ^= 1;
            }
            ++sidx; if (sidx >= 3) sidx = 0;
        }

        // SC2 folded into Q columns (SPLIT path only; colBase uniform per CTA)
        const float oscale = (SPLIT && colBase < DIM) ? SC2 : 1.0f;
        const bool  wrLo   = SPLIT && (colBase < DIM);   // lo only read for Q

        #pragma unroll
        for (int i = 0; i < 2; i++) {
            #pragma unroll
            for (int j = 0; j < 8; j++) {
                int r0 = rowBase + wm + i * 16 + (lane >> 2);
                int c0 = colBase + wn + j * 8 + (lane & 3) * 2;
                if (SPLIT) {
                    #pragma unroll
                    for (int hh = 0; hh < 2; hh++) {
                        float v0 = acc[i][j][hh * 2] * oscale, v1 = acc[i][j][hh * 2 + 1] * oscale;
                        __half2 h2 = __floats2half2_rn(v0, v1);
                        size_t idx = ((size_t)(r0 + hh * 8) * N + c0) >> 1;
                        ((uint32_t*)Chi)[idx] = *(uint32_t*)&h2;
                        if (wrLo) {
                            float l0 = v0 - __half2float(h2.x);
                            float l1 = v1 - __half2float(h2.y);
                            ((uint32_t*)Clo)[idx] = pack_hf2(l0, l1);
                        }
                    }
                } else {
                    *(float2*)&C[(size_t)r0 * N + c0]       = make_float2(acc[i][j][0], acc[i][j][1]);
                    *(float2*)&C[(size_t)(r0 + 8) * N + c0] = make_float2(acc[i][j][2], acc[i][j][3]);
                }
            }
        }
    }
}

// ---------------------------------------------------------------------------
// Flash attention, fp16 2-product, persistent CTAs over (q0, h, b) tiles.
// Stage (16KB): Khi[0,8K) Vhi[8K,16K); 2 stages + Qhi/Qlo 32KB = 64KB.
// ---------------------------------------------------------------------------
#define FST     16384
#define F_KHI   0
#define F_VHI   8192
#define FQ_OFF  (2 * FST)
#define FSMEM_TOTAL (2 * FST + 32768)

#define FLOAD_KV(sidx, c0b) do {                                               \
    uint32_t sb = sbase + (uint32_t)(sidx) * FST;                              \
    _Pragma("unroll")                                                          \
    for (int t_ = 0; t_ < 2; ++t_) {                                           \
        int v_ = tid + t_ * 256;                                               \
        int row_ = v_ >> 3, ch_ = v_ & 7;                                      \
        uint32_t sw_ = SWZ128((uint32_t)(row_ * 128 + ch_ * 16));              \
        size_t base_ = ((size_t)(bS + (c0b) + row_) * 3) * DIM + hHD + ch_ * 8;\
        CPA16(sb + F_KHI + sw_, (const char*)(qh + base_ + DIM));              \
        CPA16(sb + F_VHI + sw_, (const char*)(qh + base_ + 2 * DIM));          \
    }                                                                          \
} while (0)

__global__ __launch_bounds__(256, 2) void flash_mma(
    const __half* __restrict__ qh, const __half* __restrict__ ql,
    __half* __restrict__ Ahi, __half* __restrict__ Alo)
{
    extern __shared__ char smem[];
    const uint32_t sbase = smem_u32(smem);
    const int tid  = threadIdx.x;
    const int lane = tid & 31;
    const int wid  = tid >> 5;
    const int wrow = wid * 16;

    const int mi = lane >> 3;
    const uint32_t a_row = (mi & 1) * 8 + (lane & 7);
    const uint32_t a_ch  = (mi >> 1) * 16;
    const uint32_t b_row = (mi >> 1) * 8 + (lane & 7);
    const uint32_t b_ch  = (mi & 1) * 16;

    const int nqt = SEQ / 128;            // 16
    const int nT  = nqt * NHEAD * BATCH;  // 512
    const int ntiles = SEQ / 64;          // 32 kv tiles

    for (int tIdx = blockIdx.x; tIdx < nT; tIdx += gridDim.x) {
        const int q0  = (tIdx % nqt) * 128;
        const int h   = (tIdx / nqt) % NHEAD;
        const int b   = tIdx / (nqt * NHEAD);
        const int bS  = b * SEQ;
        const int hHD = h * HD;

        __syncthreads();   // previous tile's smem reads complete before refill

        // Q tile (hi+lo) + first KV stage
        {
            #pragma unroll
            for (int t_ = 0; t_ < 4; ++t_) {
                int v_ = tid + t_ * 256;
                int row_ = v_ >> 3, ch_ = v_ & 7;
                uint32_t sw_ = SWZ128((uint32_t)(row_ * 128 + ch_ * 16));
                size_t base_ = ((size_t)(bS + q0 + row_) * 3) * DIM + hHD + ch_ * 8;
                CPA16(sbase + FQ_OFF + sw_,         (const char*)(qh + base_));
                CPA16(sbase + FQ_OFF + 16384 + sw_, (const char*)(ql + base_));
            }
            FLOAD_KV(0, 0);
            CP_COMMIT();
        }

        float S[8][4];
        float O[8][4];
        #pragma unroll
        for (int j = 0; j < 8; j++)
            #pragma unroll
            for (int q = 0; q < 4; q++) O[j][q] = 0.f;
        float mA = -1e30f, mB = -1e30f, lA = 0.f, lB = 0.f;

        for (int tI = 0; tI < ntiles; ++tI) {
            const int s = tI & 1;
            CP_WAIT0();
            __syncthreads();
            if (tI + 1 < ntiles) { FLOAD_KV((tI + 1) & 1, (tI + 1) * 64); CP_COMMIT(); }

            const uint32_t st = sbase + (uint32_t)s * FST;

            // ---- S = Q K^T (2-product: Q exact, K hi-only) ----
            #pragma unroll
            for (int nb = 0; nb < 8; nb++)
                #pragma unroll
                for (int q = 0; q < 4; q++) S[nb][q] = 0.f;

            uint32_t Kh[2][4];
            {
                uint32_t koff = SWZ128((uint32_t)(b_row * 128) + b_ch);
                LDSM_X4(Kh[0], st + F_KHI + koff);
            }
            uint32_t qhi[4], qlo[4];
            int kb = 0;
            #pragma unroll
            for (int it = 0; it < 16; it++) {           // it = dks*4 + nbp
                const int dks = it >> 2, nbp = it & 3;
                if (nbp == 0) {
                    uint32_t qoff = SWZ128((uint32_t)((wrow + a_row) * 128 + dks * 32) + a_ch);
                    LDSM_X4(qhi, sbase + FQ_OFF + qoff);
                    LDSM_X4(qlo, sbase + FQ_OFF + 16384 + qoff);
                }
                if (it + 1 < 16) {
                    const int nd = (it + 1) >> 2, nn = (it + 1) & 3;
                    uint32_t koff = SWZ128((uint32_t)((nn * 16 + b_row) * 128 + nd * 32) + b_ch);
                    LDSM_X4(Kh[kb ^ 1], st + F_KHI + koff);
                }
                float* s0 = S[nbp * 2 + 0];
                float* s1 = S[nbp * 2 + 1];
                MMA16816(s0, qhi, (&Kh[kb][0]));
                MMA16816(s1, qhi, (&Kh[kb][2]));
                MMA16816(s0, qlo, (&Kh[kb][0]));
                MMA16816(s1, qlo, (&Kh[kb][2]));
                kb ^= 1;
            }

            // ---- row max + O rescale ----
            float mxA = -1e30f, mxB = -1e30f;
            #pragma unroll
            for (int nb = 0; nb < 8; nb++) {
                mxA = fmaxf(mxA, fmaxf(S[nb][0], S[nb][1]));
                mxB = fmaxf(mxB, fmaxf(S[nb][2], S[nb][3]));
            }
            #pragma unroll
            for (int d = 1; d <= 2; d <<= 1) {
                mxA = fmaxf(mxA, __shfl_xor_sync(0xffffffffu, mxA, d));
                mxB = fmaxf(mxB, __shfl_xor_sync(0xffffffffu, mxB, d));
            }
            float mAn = fmaxf(mA, mxA), mBn = fmaxf(mB, mxB);
            float fA = ex2f(mA - mAn),  fB = ex2f(mB - mBn);
            #pragma unroll
            for (int j = 0; j < 8; j++) {
                O[j][0] *= fA; O[j][1] *= fA; O[j][2] *= fB; O[j][3] *= fB;
            }

            // ---- PV (2-product: P exact, V hi-only; exp interleaved) ----
            float sA = 0.f, sB = 0.f;
            uint32_t Vh[2][4];
            {
                uint32_t voff = SWZ128((uint32_t)(a_row * 128) + a_ch);
                LDSM_X4T(Vh[0], st + F_VHI + voff);
            }
            uint32_t ph[4], pl[4];
            int vb = 0;
            #pragma unroll
            for (int it = 0; it < 16; it++) {           // it = ks*4 + dg
                const int ks = it >> 2, dg = it & 3;
                if (dg == 0) {
                    float pv[2][4];
                    #pragma unroll
                    for (int jj = 0; jj < 2; jj++) {
                        const float* sv = S[ks * 2 + jj];
                        pv[jj][0] = ex2f(sv[0] - mAn);
                        pv[jj][1] = ex2f(sv[1] - mAn);
                        pv[jj][2] = ex2f(sv[2] - mBn);
                        pv[jj][3] = ex2f(sv[3] - mBn);
                        sA += pv[jj][0] + pv[jj][1];
                        sB += pv[jj][2] + pv[jj][3];
                    }
                    #pragma unroll
                    for (int u = 0; u < 4; u++) {
                        const float* sv = pv[u >> 1];
                        float x0 = sv[(u & 1) * 2], x1 = sv[(u & 1) * 2 + 1];
                        __half2 h2 = __floats2half2_rn(x0, x1);
                        ph[u] = *(uint32_t*)&h2;
                        pl[u] = pack_hf2(x0 - __half2float(h2.x), x1 - __half2float(h2.y));
                    }
                }
                if (it + 1 < 16) {
                    const int nks = (it + 1) >> 2, ndg = (it + 1) & 3;
                    uint32_t voff = SWZ128((uint32_t)((nks * 16 + a_row) * 128 + ndg * 32) + a_ch);
                    LDSM_X4T(Vh[vb ^ 1], st + F_VHI + voff);
                }
                float* o0 = O[dg * 2 + 0];
                float* o1 = O[dg * 2 + 1];
                MMA16816(o0, ph, (&Vh[vb][0]));
                MMA16816(o1, ph, (&Vh[vb][2]));
                MMA16816(o0, pl, (&Vh[vb][0]));
                MMA16816(o1, pl, (&Vh[vb][2]));
                vb ^= 1;
            }
            #pragma unroll
            for (int d = 1; d <= 2; d <<= 1) {
                sA += __shfl_xor_sync(0xffffffffu, sA, d);
                sB += __shfl_xor_sync(0xffffffffu, sB, d);
            }
            lA = lA * fA + sA;  lB = lB * fB + sB;
            mA = mAn;           mB = mBn;
        }

        // ---- epilogue: normalize, split to fp16 hi/lo, store ----
        float invA = 1.f / lA, invB = 1.f / lB;
        int rA = bS + q0 + wrow + (lane >> 2);
        int rB = rA + 8;
        #pragma unroll
        for (int j = 0; j < 8; j++) {
            int d0 = j * 8 + (lane & 3) * 2;
            float a0 = O[j][0] * invA, a1 = O[j][1] * invA;
            float b0 = O[j][2] * invB, b1 = O[j][3] * invB;
            __half2 hA = __floats2half2_rn(a0, a1);
            __half2 hB = __floats2half2_rn(b0, b1);
            size_t iA = ((size_t)rA * DIM + hHD + d0) >> 1;
            size_t iB = ((size_t)rB * DIM + hHD + d0) >> 1;
            ((uint32_t*)Ahi)[iA] = *(uint32_t*)&hA;
            ((uint32_t*)Ahi)[iB] = *(uint32_t*)&hB;
            ((uint32_t*)Alo)[iA] = pack_hf2(a0 - __half2float(hA.x), a1 - __half2float(hA.y));
            ((uint32_t*)Alo)[iB] = pack_hf2(b0 - __half2float(hB.x), b1 - __half2float(hB.y));
        }
    }
}

// ---------------------------------------------------------------------------
extern "C" void kernel_launch(void* const* d_in, const int* in_sizes, int n_in,
                              void* d_out, int out_size)
{
    const float* x     = (const float*)d_in[0];
    const float* Wqkv  = (const float*)d_in[1];
    const float* Wproj = (const float*)d_in[2];
    float* out = (float*)d_out;

    __half *xhi, *xlo, *qh, *ql, *ahi, *alo, *wqh, *wph;
    cudaGetSymbolAddress((void**)&xhi, g_xhi);
    cudaGetSymbolAddress((void**)&xlo, g_xlo);
    cudaGetSymbolAddress((void**)&qh,  g_qh);
    cudaGetSymbolAddress((void**)&ql,  g_ql);
    cudaGetSymbolAddress((void**)&ahi, g_ahi);
    cudaGetSymbolAddress((void**)&alo, g_alo);
    cudaGetSymbolAddress((void**)&wqh, g_wqh);
    cudaGetSymbolAddress((void**)&wph, g_wph);

    const int M = BATCH * SEQ;          // 4096

    cudaFuncSetAttribute(gemm_mma<true>,  cudaFuncAttributeMaxDynamicSharedMemorySize, GSMEM_TOTAL);
    cudaFuncSetAttribute(gemm_mma<false>, cudaFuncAttributeMaxDynamicSharedMemorySize, GSMEM_TOTAL);
    cudaFuncSetAttribute(flash_mma,       cudaFuncAttributeMaxDynamicSharedMemorySize, FSMEM_TOTAL);

    // 0) splits / weight transposes (hi only)
    split_kernel<<<(M * DIM / 4 + 255) / 256, 256>>>(x, xhi, xlo, M * DIM / 4);
    {
        dim3 g1(3 * DIM / 32, DIM / 32);
        transpose_h<<<g1, 256>>>(Wqkv, wqh, DIM, 3 * DIM);
        dim3 g2(DIM / 32, DIM / 32);
        transpose_h<<<g2, 256>>>(Wproj, wph, DIM, DIM);
    }

    // 1) qkv = x @ Wqkv -> fp16 hi/lo (Q pre-scaled by SC2), persistent grid
    {
        int tiles = (3 * DIM / 128) * (M / 128);       // 768
        int grid  = tiles < NSLOTS ? tiles : NSLOTS;
        gemm_mma<true><<<grid, 256, GSMEM_TOTAL>>>(xhi, xlo, wqh,
                                                   nullptr, qh, ql, M, 3 * DIM, DIM);
    }

    // 2) flash attention -> fp16 hi/lo, persistent grid
    {
        int tiles = (SEQ / 128) * NHEAD * BATCH;       // 512
        int grid  = tiles < NSLOTS ? tiles : NSLOTS;
        flash_mma<<<grid, 256, FSMEM_TOTAL>>>(qh, ql, ahi, alo);
    }

    // 3) out = attn @ Wproj (fp32 out)
    {
        int tiles = (DIM / 128) * (M / 128);           // 256
        int grid  = tiles < NSLOTS ? tiles : NSLOTS;
        gemm_mma<false><<<grid, 256, GSMEM_TOTAL>>>(ahi, alo, wph,
                                                    out, nullptr, nullptr, M, DIM, DIM);
    }
}

// round 13
// speedup vs baseline: 1.0333x; 1.0333x over previous
#include <cuda_runtime.h>
#include <cuda_fp16.h>
#include <cstdint>
#include <cstddef>

#define BATCH 2
#define SEQ   2048
#define DIM   1024
#define NHEAD 16
#define HD    64
// SCALE * log2(e): logits kept in base-2 domain (folded into Q at QKV epilogue)
#define SC2   0.18033688011112042f

#define NSLOTS 296   // 148 SMs x 2 CTAs/SM

// ---------------------------------------------------------------------------
// Scratch (allocation-free rule: __device__ globals) — fp16 scheme
// ---------------------------------------------------------------------------
__device__ __half g_xhi[(size_t)BATCH * SEQ * DIM];
__device__ __half g_xlo[(size_t)BATCH * SEQ * DIM];
__device__ __half g_qh [(size_t)BATCH * SEQ * 3 * DIM];   // qkv hi
__device__ __half g_ql [(size_t)BATCH * SEQ * 3 * DIM];   // qkv lo (only Q read)
__device__ __half g_ahi[(size_t)BATCH * SEQ * DIM];       // attn hi
__device__ __half g_alo[(size_t)BATCH * SEQ * DIM];       // attn lo
__device__ __half g_wqh[(size_t)3 * DIM * DIM];           // [3072,1024] K-major, hi only
__device__ __half g_wph[(size_t)DIM * DIM];               // [1024,1024] K-major, hi only

// ---------------------------------------------------------------------------
// Portable PTX helpers
// ---------------------------------------------------------------------------
__device__ __forceinline__ uint32_t smem_u32(const void* p) {
    uint32_t a;
    asm("{ .reg .u64 t; cvta.to.shared.u64 t, %1; cvt.u32.u64 %0, t; }" : "=r"(a) : "l"(p));
    return a;
}
#define CPA16(dst, src) \
    asm volatile("cp.async.cg.shared.global [%0], [%1], 16;" :: "r"(dst), "l"(src) : "memory")
#define CP_COMMIT() asm volatile("cp.async.commit_group;" ::: "memory")
#define CP_WAIT0()  asm volatile("cp.async.wait_group 0;" ::: "memory")
#define CP_WAIT1()  asm volatile("cp.async.wait_group 1;" ::: "memory")

#define LDSM_X4(r, addr) \
    asm volatile("ldmatrix.sync.aligned.m8n8.x4.shared.b16 {%0,%1,%2,%3}, [%4];" \
        : "=r"((r)[0]), "=r"((r)[1]), "=r"((r)[2]), "=r"((r)[3]) : "r"(addr))
#define LDSM_X4T(r, addr) \
    asm volatile("ldmatrix.sync.aligned.m8n8.x4.trans.shared.b16 {%0,%1,%2,%3}, [%4];" \
        : "=r"((r)[0]), "=r"((r)[1]), "=r"((r)[2]), "=r"((r)[3]) : "r"(addr))

// fp16 HMMA, fp32 accumulate
#define MMA16816(c, a, b) \
    asm volatile("mma.sync.aligned.m16n8k16.row.col.f32.f16.f16.f32 " \
        "{%0,%1,%2,%3}, {%4,%5,%6,%7}, {%8,%9}, {%0,%1,%2,%3};" \
        : "+f"((c)[0]), "+f"((c)[1]), "+f"((c)[2]), "+f"((c)[3]) \
        : "r"((a)[0]), "r"((a)[1]), "r"((a)[2]), "r"((a)[3]), "r"((b)[0]), "r"((b)[1]))

#define SWZ64(off)  ((off) ^ (((off) >> 3) & 0x30))
#define SWZ128(off) ((off) ^ (((off) >> 3) & 0x70))

__device__ __forceinline__ float ex2f(float x) {
    float y; asm("ex2.approx.ftz.f32 %0, %1;" : "=f"(y) : "f"(x)); return y;
}
__device__ __forceinline__ uint32_t pack_hf2(float a, float b) {
    __half2 h = __floats2half2_rn(a, b);
    return *(uint32_t*)&h;
}

// ---------------------------------------------------------------------------
// Preprocessing
// ---------------------------------------------------------------------------
__global__ __launch_bounds__(256) void split_kernel(
    const float* __restrict__ X, __half* __restrict__ hi,
    __half* __restrict__ lo, int n4)
{
    int i = blockIdx.x * blockDim.x + threadIdx.x;
    if (i >= n4) return;
    float4 v = ((const float4*)X)[i];
    __half h[4], l[4];
    float f[4] = {v.x, v.y, v.z, v.w};
    #pragma unroll
    for (int j = 0; j < 4; j++) {
        h[j] = __float2half_rn(f[j]);
        l[j] = __float2half_rn(f[j] - __half2float(h[j]));
    }
    ((uint2*)hi)[i] = *(uint2*)h;
    ((uint2*)lo)[i] = *(uint2*)l;
}

// W [K, N] fp32 -> T [N, K] fp16 hi only (transpose + quantize)
__global__ __launch_bounds__(256) void transpose_h(
    const float* __restrict__ W, __half* __restrict__ Th, int K, int N)
{
    __shared__ float tile[32][33];
    int tx = threadIdx.x & 31, ty = threadIdx.x >> 5;
    int k0 = blockIdx.y * 32, n0 = blockIdx.x * 32;
    #pragma unroll
    for (int i = 0; i < 32; i += 8)
        tile[ty + i][tx] = W[(size_t)(k0 + ty + i) * N + n0 + tx];
    __syncthreads();
    #pragma unroll
    for (int i = 0; i < 32; i += 8) {
        float v = tile[tx][ty + i];
        Th[(size_t)(n0 + ty + i) * K + k0 + tx] = __float2half_rn(v);
    }
}

// ---------------------------------------------------------------------------
// HMMA fp16 2-product GEMM (persistent CTAs): C = (Ahi+Alo)[M,K] @ Bh[N,K]^T
// CTA tile 128x128, BK=32, 3-stage cp.async, 2 CTAs/SM, tile loop per CTA.
// Stage (24KB): Ahi[0,8K) Alo[8K,16K) Bh[16K,24K)
// ---------------------------------------------------------------------------
#define GST 24576
#define GSMEM_TOTAL (3 * GST)

#define LOAD_STAGE(sidx, kc) do {                                              \
    uint32_t sb = sbase + (uint32_t)(sidx) * GST;                              \
    _Pragma("unroll")                                                          \
    for (int t_ = 0; t_ < 2; ++t_) {                                           \
        int v_ = tid + t_ * 256;                                               \
        int row_ = v_ >> 2, cb_ = v_ & 3;                                      \
        uint32_t sw_ = SWZ64((uint32_t)(row_ * 64 + cb_ * 16));                \
        size_t gA_ = (size_t)(rowBase + row_) * K + (kc) + cb_ * 8;            \
        size_t gB_ = (size_t)(colBase + row_) * K + (kc) + cb_ * 8;            \
        CPA16(sb + sw_,         (const char*)(Ahi + gA_));                     \
        CPA16(sb + 8192  + sw_, (const char*)(Alo + gA_));                     \
        CPA16(sb + 16384 + sw_, (const char*)(Bh + gB_));                      \
    }                                                                          \
} while (0)

template <bool SPLIT>
__global__ __launch_bounds__(256, 2) void gemm_mma(
    const __half* __restrict__ Ahi, const __half* __restrict__ Alo,
    const __half* __restrict__ Bh,
    float* __restrict__ C, __half* __restrict__ Chi,
    __half* __restrict__ Clo, int M, int N, int K)
{
    extern __shared__ char smem[];
    const uint32_t sbase = smem_u32(smem);
    const int tid  = threadIdx.x;
    const int lane = tid & 31;
    const int wid  = tid >> 5;
    const int wm = (wid & 3) * 32;
    const int wn = (wid >> 2) * 64;

    const int mi = lane >> 3;
    const uint32_t a_off = (uint32_t)((((mi & 1) * 8 + (lane & 7)) * 64) + (mi >> 1) * 16);
    const uint32_t b_off = (uint32_t)((((mi >> 1) * 8 + (lane & 7)) * 64) + (mi & 1) * 16);

    const int ntx = N / 128;
    const int ntiles = ntx * (M / 128);
    const int nk = K / 32;                 // 32

    for (int tIdx = blockIdx.x; tIdx < ntiles; tIdx += gridDim.x) {
        const int rowBase = (tIdx / ntx) * 128;
        const int colBase = (tIdx % ntx) * 128;

        float acc[2][8][4];
        #pragma unroll
        for (int i = 0; i < 2; i++)
            #pragma unroll
            for (int j = 0; j < 8; j++)
                #pragma unroll
                for (int q = 0; q < 4; q++) acc[i][j][q] = 0.f;

        __syncthreads();   // previous tile's smem reads complete before refill
        LOAD_STAGE(0, 0);  CP_COMMIT();
        LOAD_STAGE(1, 32); CP_COMMIT();

        int sidx = 0;
        for (int c = 0; c < nk; ++c) {
            if (c + 1 < nk) { CP_WAIT1(); } else { CP_WAIT0(); }
            __syncthreads();
            if (c + 2 < nk) {
                int ns = sidx + 2; if (ns >= 3) ns -= 3;
                LOAD_STAGE(ns, (c + 2) * 32);
                CP_COMMIT();
            }

            const uint32_t st = sbase + (uint32_t)sidx * GST;

            // hoist all A fragments for this chunk (both kb halves)
            uint32_t Ah[2][2][4], Al[2][2][4];
            #pragma unroll
            for (int kb2 = 0; kb2 < 2; kb2++)
                #pragma unroll
                for (int i = 0; i < 2; i++) {
                    uint32_t off = (uint32_t)((wm + i * 16) * 64 + kb2 * 32) + a_off;
                    LDSM_X4(Ah[kb2][i], st + SWZ64(off));
                    LDSM_X4(Al[kb2][i], st + 8192 + SWZ64(off));
                }

            // B fragments double-buffered across the flattened (kb, jp) loop
            uint32_t Bf[2][4];
            {
                uint32_t off = (uint32_t)(wn * 64) + b_off;   // kb=0, jp=0
                LDSM_X4(Bf[0], st + 16384 + SWZ64(off));
            }
            int bb = 0;
            #pragma unroll
            for (int it = 0; it < 8; it++) {            // it = kb*4 + jp
                const int kb = it >> 2, jp = it & 3;
                if (it + 1 < 8) {
                    const int nkb = (it + 1) >> 2, njp = (it + 1) & 3;
                    uint32_t off = (uint32_t)((wn + njp * 16) * 64 + nkb * 32) + b_off;
                    LDSM_X4(Bf[bb ^ 1], st + 16384 + SWZ64(off));
                }
                // 2-product: A-side exact, B-side fp16
                #pragma unroll
                for (int i = 0; i < 2; i++)
                    #pragma unroll
                    for (int jj = 0; jj < 2; jj++)
                        MMA16816(acc[i][jp * 2 + jj], Ah[kb][i], (&Bf[bb][jj * 2]));
                #pragma unroll
                for (int i = 0; i < 2; i++)
                    #pragma unroll
                    for (int jj = 0; jj < 2; jj++)
                        MMA16816(acc[i][jp * 2 + jj], Al[kb][i], (&Bf[bb][jj * 2]));
                bb ^= 1;
            }
            ++sidx; if (sidx >= 3) sidx = 0;
        }

        // SC2 folded into Q columns (SPLIT path only; colBase uniform per CTA)
        const float oscale = (SPLIT && colBase < DIM) ? SC2 : 1.0f;
        const bool  wrLo   = SPLIT && (colBase < DIM);   // lo only read for Q

        #pragma unroll
        for (int i = 0; i < 2; i++) {
            #pragma unroll
            for (int j = 0; j < 8; j++) {
                int r0 = rowBase + wm + i * 16 + (lane >> 2);
                int c0 = colBase + wn + j * 8 + (lane & 3) * 2;
                if (SPLIT) {
                    #pragma unroll
                    for (int hh = 0; hh < 2; hh++) {
                        float v0 = acc[i][j][hh * 2] * oscale, v1 = acc[i][j][hh * 2 + 1] * oscale;
                        __half2 h2 = __floats2half2_rn(v0, v1);
                        size_t idx = ((size_t)(r0 + hh * 8) * N + c0) >> 1;
                        ((uint32_t*)Chi)[idx] = *(uint32_t*)&h2;
                        if (wrLo) {
                            float l0 = v0 - __half2float(h2.x);
                            float l1 = v1 - __half2float(h2.y);
                            ((uint32_t*)Clo)[idx] = pack_hf2(l0, l1);
                        }
                    }
                } else {
                    *(float2*)&C[(size_t)r0 * N + c0]       = make_float2(acc[i][j][0], acc[i][j][1]);
                    *(float2*)&C[(size_t)(r0 + 8) * N + c0] = make_float2(acc[i][j][2], acc[i][j][3]);
                }
            }
        }
    }
}

// ---------------------------------------------------------------------------
// Flash attention, fp16 2-product. CTA = 128 q rows of one (b,h); 8 warps.
// 3-stage KV pipeline: stage 16KB (Khi|Vhi), 3 stages + Qhi/Qlo 32KB = 80KB.
// Non-persistent grid (512 CTAs) — persistence regressed here (R12).
// ---------------------------------------------------------------------------
#define FST     16384
#define F_KHI   0
#define F_VHI   8192
#define FQ_OFF  (3 * FST)
#define FSMEM_TOTAL (3 * FST + 32768)

#define FLOAD_KV(sidx, c0b) do {                                               \
    uint32_t sb = sbase + (uint32_t)(sidx) * FST;                              \
    _Pragma("unroll")                                                          \
    for (int t_ = 0; t_ < 2; ++t_) {                                           \
        int v_ = tid + t_ * 256;                                               \
        int row_ = v_ >> 3, ch_ = v_ & 7;                                      \
        uint32_t sw_ = SWZ128((uint32_t)(row_ * 128 + ch_ * 16));              \
        size_t base_ = ((size_t)(bS + (c0b) + row_) * 3) * DIM + hHD + ch_ * 8;\
        CPA16(sb + F_KHI + sw_, (const char*)(qh + base_ + DIM));              \
        CPA16(sb + F_VHI + sw_, (const char*)(qh + base_ + 2 * DIM));          \
    }                                                                          \
} while (0)

__global__ __launch_bounds__(256, 2) void flash_mma(
    const __half* __restrict__ qh, const __half* __restrict__ ql,
    __half* __restrict__ Ahi, __half* __restrict__ Alo)
{
    extern __shared__ char smem[];
    const uint32_t sbase = smem_u32(smem);
    const int tid  = threadIdx.x;
    const int lane = tid & 31;
    const int wid  = tid >> 5;
    const int wrow = wid * 16;
    const int h  = blockIdx.y;
    const int b  = blockIdx.z;
    const int q0 = blockIdx.x * 128;
    const int bS  = b * SEQ;
    const int hHD = h * HD;

    const int mi = lane >> 3;
    const uint32_t a_row = (mi & 1) * 8 + (lane & 7);
    const uint32_t a_ch  = (mi >> 1) * 16;
    const uint32_t b_row = (mi >> 1) * 8 + (lane & 7);
    const uint32_t b_ch  = (mi & 1) * 16;

    // Q tile (hi+lo) + KV stages 0,1 (two commit groups in flight)
    {
        #pragma unroll
        for (int t_ = 0; t_ < 4; ++t_) {
            int v_ = tid + t_ * 256;
            int row_ = v_ >> 3, ch_ = v_ & 7;
            uint32_t sw_ = SWZ128((uint32_t)(row_ * 128 + ch_ * 16));
            size_t base_ = ((size_t)(bS + q0 + row_) * 3) * DIM + hHD + ch_ * 8;
            CPA16(sbase + FQ_OFF + sw_,         (const char*)(qh + base_));
            CPA16(sbase + FQ_OFF + 16384 + sw_, (const char*)(ql + base_));
        }
        FLOAD_KV(0, 0);
        CP_COMMIT();
        FLOAD_KV(1, 64);
        CP_COMMIT();
    }

    float S[8][4];
    float O[8][4];
    #pragma unroll
    for (int j = 0; j < 8; j++)
        #pragma unroll
        for (int q = 0; q < 4; q++) O[j][q] = 0.f;
    float mA = -1e30f, mB = -1e30f, lA = 0.f, lB = 0.f;

    const int ntiles = SEQ / 64;   // 32
    int sidx = 0;                  // stage of tile tI (mod 3)

    for (int tI = 0; tI < ntiles; ++tI) {
        if (tI + 1 < ntiles) { CP_WAIT1(); } else { CP_WAIT0(); }
        __syncthreads();           // all warps done reading stage (tI+2)%3
        if (tI + 2 < ntiles) {
            int ns = sidx + 2; if (ns >= 3) ns -= 3;
            FLOAD_KV(ns, (tI + 2) * 64);
            CP_COMMIT();
        }

        const uint32_t st = sbase + (uint32_t)sidx * FST;

        // ---- S = Q K^T (2-product: Q exact, K hi-only) ----
        #pragma unroll
        for (int nb = 0; nb < 8; nb++)
            #pragma unroll
            for (int q = 0; q < 4; q++) S[nb][q] = 0.f;

        uint32_t Kh[2][4];
        {
            uint32_t koff = SWZ128((uint32_t)(b_row * 128) + b_ch);   // dks=0, nbp=0
            LDSM_X4(Kh[0], st + F_KHI + koff);
        }
        uint32_t qhi[4], qlo[4];
        int kb = 0;
        #pragma unroll
        for (int it = 0; it < 16; it++) {           // it = dks*4 + nbp
            const int dks = it >> 2, nbp = it & 3;
            if (nbp == 0) {
                uint32_t qoff = SWZ128((uint32_t)((wrow + a_row) * 128 + dks * 32) + a_ch);
                LDSM_X4(qhi, sbase + FQ_OFF + qoff);
                LDSM_X4(qlo, sbase + FQ_OFF + 16384 + qoff);
            }
            if (it + 1 < 16) {
                const int nd = (it + 1) >> 2, nn = (it + 1) & 3;
                uint32_t koff = SWZ128((uint32_t)((nn * 16 + b_row) * 128 + nd * 32) + b_ch);
                LDSM_X4(Kh[kb ^ 1], st + F_KHI + koff);
            }
            float* s0 = S[nbp * 2 + 0];
            float* s1 = S[nbp * 2 + 1];
            MMA16816(s0, qhi, (&Kh[kb][0]));
            MMA16816(s1, qhi, (&Kh[kb][2]));
            MMA16816(s0, qlo, (&Kh[kb][0]));
            MMA16816(s1, qlo, (&Kh[kb][2]));
            kb ^= 1;
        }

        // ---- row max + O rescale ----
        float mxA = -1e30f, mxB = -1e30f;
        #pragma unroll
        for (int nb = 0; nb < 8; nb++) {
            mxA = fmaxf(mxA, fmaxf(S[nb][0], S[nb][1]));
            mxB = fmaxf(mxB, fmaxf(S[nb][2], S[nb][3]));
        }
        #pragma unroll
        for (int d = 1; d <= 2; d <<= 1) {
            mxA = fmaxf(mxA, __shfl_xor_sync(0xffffffffu, mxA, d));
            mxB = fmaxf(mxB, __shfl_xor_sync(0xffffffffu, mxB, d));
        }
        float mAn = fmaxf(mA, mxA), mBn = fmaxf(mB, mxB);
        float fA = ex2f(mA - mAn),  fB = ex2f(mB - mBn);
        #pragma unroll
        for (int j = 0; j < 8; j++) {
            O[j][0] *= fA; O[j][1] *= fA; O[j][2] *= fB; O[j][3] *= fB;
        }

        // ---- PV (2-product: P exact, V hi-only; exp interleaved) ----
        float sA = 0.f, sB = 0.f;
        uint32_t Vh[2][4];
        {
            uint32_t voff = SWZ128((uint32_t)(a_row * 128) + a_ch);   // ks=0, dg=0
            LDSM_X4T(Vh[0], st + F_VHI + voff);
        }
        uint32_t ph[4], pl[4];
        int vb = 0;
        #pragma unroll
        for (int it = 0; it < 16; it++) {           // it = ks*4 + dg
            const int ks = it >> 2, dg = it & 3;
            if (dg == 0) {
                float pv[2][4];
                #pragma unroll
                for (int jj = 0; jj < 2; jj++) {
                    const float* sv = S[ks * 2 + jj];
                    pv[jj][0] = ex2f(sv[0] - mAn);
                    pv[jj][1] = ex2f(sv[1] - mAn);
                    pv[jj][2] = ex2f(sv[2] - mBn);
                    pv[jj][3] = ex2f(sv[3] - mBn);
                    sA += pv[jj][0] + pv[jj][1];
                    sB += pv[jj][2] + pv[jj][3];
                }
                #pragma unroll
                for (int u = 0; u < 4; u++) {
                    const float* sv = pv[u >> 1];
                    float x0 = sv[(u & 1) * 2], x1 = sv[(u & 1) * 2 + 1];
                    __half2 h2 = __floats2half2_rn(x0, x1);
                    ph[u] = *(uint32_t*)&h2;
                    pl[u] = pack_hf2(x0 - __half2float(h2.x), x1 - __half2float(h2.y));
                }
            }
            if (it + 1 < 16) {
                const int nks = (it + 1) >> 2, ndg = (it + 1) & 3;
                uint32_t voff = SWZ128((uint32_t)((nks * 16 + a_row) * 128 + ndg * 32) + a_ch);
                LDSM_X4T(Vh[vb ^ 1], st + F_VHI + voff);
            }
            float* o0 = O[dg * 2 + 0];
            float* o1 = O[dg * 2 + 1];
            MMA16816(o0, ph, (&Vh[vb][0]));
            MMA16816(o1, ph, (&Vh[vb][2]));
            MMA16816(o0, pl, (&Vh[vb][0]));
            MMA16816(o1, pl, (&Vh[vb][2]));
            vb ^= 1;
        }
        #pragma unroll
        for (int d = 1; d <= 2; d <<= 1) {
            sA += __shfl_xor_sync(0xffffffffu, sA, d);
            sB += __shfl_xor_sync(0xffffffffu, sB, d);
        }
        lA = lA * fA + sA;  lB = lB * fB + sB;
        mA = mAn;           mB = mBn;

        ++sidx; if (sidx >= 3) sidx = 0;
    }

    // ---- epilogue: normalize, split to fp16 hi/lo, store ----
    float invA = 1.f / lA, invB = 1.f / lB;
    int rA = bS + q0 + wrow + (lane >> 2);
    int rB = rA + 8;
    #pragma unroll
    for (int j = 0; j < 8; j++) {
        int d0 = j * 8 + (lane & 3) * 2;
        float a0 = O[j][0] * invA, a1 = O[j][1] * invA;
        float b0 = O[j][2] * invB, b1 = O[j][3] * invB;
        __half2 hA = __floats2half2_rn(a0, a1);
        __half2 hB = __floats2half2_rn(b0, b1);
        size_t iA = ((size_t)rA * DIM + hHD + d0) >> 1;
        size_t iB = ((size_t)rB * DIM + hHD + d0) >> 1;
        ((uint32_t*)Ahi)[iA] = *(uint32_t*)&hA;
        ((uint32_t*)Ahi)[iB] = *(uint32_t*)&hB;
        ((uint32_t*)Alo)[iA] = pack_hf2(a0 - __half2float(hA.x), a1 - __half2float(hA.y));
        ((uint32_t*)Alo)[iB] = pack_hf2(b0 - __half2float(hB.x), b1 - __half2float(hB.y));
    }
}

// ---------------------------------------------------------------------------
extern "C" void kernel_launch(void* const* d_in, const int* in_sizes, int n_in,
                              void* d_out, int out_size)
{
    const float* x     = (const float*)d_in[0];
    const float* Wqkv  = (const float*)d_in[1];
    const float* Wproj = (const float*)d_in[2];
    float* out = (float*)d_out;

    __half *xhi, *xlo, *qh, *ql, *ahi, *alo, *wqh, *wph;
    cudaGetSymbolAddress((void**)&xhi, g_xhi);
    cudaGetSymbolAddress((void**)&xlo, g_xlo);
    cudaGetSymbolAddress((void**)&qh,  g_qh);
    cudaGetSymbolAddress((void**)&ql,  g_ql);
    cudaGetSymbolAddress((void**)&ahi, g_ahi);
    cudaGetSymbolAddress((void**)&alo, g_alo);
    cudaGetSymbolAddress((void**)&wqh, g_wqh);
    cudaGetSymbolAddress((void**)&wph, g_wph);

    const int M = BATCH * SEQ;          // 4096

    cudaFuncSetAttribute(gemm_mma<true>,  cudaFuncAttributeMaxDynamicSharedMemorySize, GSMEM_TOTAL);
    cudaFuncSetAttribute(gemm_mma<false>, cudaFuncAttributeMaxDynamicSharedMemorySize, GSMEM_TOTAL);
    cudaFuncSetAttribute(flash_mma,       cudaFuncAttributeMaxDynamicSharedMemorySize, FSMEM_TOTAL);

    // 0) splits / weight transposes (hi only)
    split_kernel<<<(M * DIM / 4 + 255) / 256, 256>>>(x, xhi, xlo, M * DIM / 4);
    {
        dim3 g1(3 * DIM / 32, DIM / 32);
        transpose_h<<<g1, 256>>>(Wqkv, wqh, DIM, 3 * DIM);
        dim3 g2(DIM / 32, DIM / 32);
        transpose_h<<<g2, 256>>>(Wproj, wph, DIM, DIM);
    }

    // 1) qkv = x @ Wqkv -> fp16 hi/lo (Q pre-scaled by SC2), persistent grid
    {
        int tiles = (3 * DIM / 128) * (M / 128);       // 768
        int grid  = tiles < NSLOTS ? tiles : NSLOTS;
        gemm_mma<true><<<grid, 256, GSMEM_TOTAL>>>(xhi, xlo, wqh,
                                                   nullptr, qh, ql, M, 3 * DIM, DIM);
    }

    // 2) flash attention -> fp16 hi/lo, non-persistent grid (R12 post-mortem)
    {
        dim3 grid(SEQ / 128, NHEAD, BATCH);
        flash_mma<<<grid, 256, FSMEM_TOTAL>>>(qh, ql, ahi, alo);
    }

    // 3) out = attn @ Wproj (fp32 out), persistent grid (sub-wave anyway)
    {
        int tiles = (DIM / 128) * (M / 128);           // 256
        int grid  = tiles < NSLOTS ? tiles : NSLOTS;
        gemm_mma<false><<<grid, 256, GSMEM_TOTAL>>>(ahi, alo, wph,
                                                    out, nullptr, nullptr, M, DIM, DIM);
    }
}

// round 14
// speedup vs baseline: 1.1469x; 1.1099x over previous
#include <cuda_runtime.h>
#include <cuda_fp16.h>
#include <cstdint>
#include <cstddef>

#define BATCH 2
#define SEQ   2048
#define DIM   1024
#define NHEAD 16
#define HD    64
// SCALE * log2(e): logits kept in base-2 domain (folded into Q at QKV epilogue)
#define SC2   0.18033688011112042f

#define NSLOTS 296   // 148 SMs x 2 CTAs/SM

// ---------------------------------------------------------------------------
// Scratch (allocation-free rule: __device__ globals) — fp16 scheme
// ---------------------------------------------------------------------------
__device__ __half g_xhi[(size_t)BATCH * SEQ * DIM];
__device__ __half g_xlo[(size_t)BATCH * SEQ * DIM];
__device__ __half g_qh [(size_t)BATCH * SEQ * 3 * DIM];   // qkv hi
__device__ __half g_ql [(size_t)BATCH * SEQ * 3 * DIM];   // qkv lo (only Q read)
__device__ __half g_ahi[(size_t)BATCH * SEQ * DIM];       // attn hi
__device__ __half g_alo[(size_t)BATCH * SEQ * DIM];       // attn lo
__device__ __half g_wqh[(size_t)3 * DIM * DIM];           // [3072,1024] K-major, hi only
__device__ __half g_wph[(size_t)DIM * DIM];               // [1024,1024] K-major, hi only

// ---------------------------------------------------------------------------
// Portable PTX helpers
// ---------------------------------------------------------------------------
__device__ __forceinline__ uint32_t smem_u32(const void* p) {
    uint32_t a;
    asm("{ .reg .u64 t; cvta.to.shared.u64 t, %1; cvt.u32.u64 %0, t; }" : "=r"(a) : "l"(p));
    return a;
}
#define CPA16(dst, src) \
    asm volatile("cp.async.cg.shared.global [%0], [%1], 16;" :: "r"(dst), "l"(src) : "memory")
#define CP_COMMIT() asm volatile("cp.async.commit_group;" ::: "memory")
#define CP_WAIT0()  asm volatile("cp.async.wait_group 0;" ::: "memory")
#define CP_WAIT1()  asm volatile("cp.async.wait_group 1;" ::: "memory")

#define LDSM_X4(r, addr) \
    asm volatile("ldmatrix.sync.aligned.m8n8.x4.shared.b16 {%0,%1,%2,%3}, [%4];" \
        : "=r"((r)[0]), "=r"((r)[1]), "=r"((r)[2]), "=r"((r)[3]) : "r"(addr))
#define LDSM_X4T(r, addr) \
    asm volatile("ldmatrix.sync.aligned.m8n8.x4.trans.shared.b16 {%0,%1,%2,%3}, [%4];" \
        : "=r"((r)[0]), "=r"((r)[1]), "=r"((r)[2]), "=r"((r)[3]) : "r"(addr))

// fp16 HMMA, fp32 accumulate
#define MMA16816(c, a, b) \
    asm volatile("mma.sync.aligned.m16n8k16.row.col.f32.f16.f16.f32 " \
        "{%0,%1,%2,%3}, {%4,%5,%6,%7}, {%8,%9}, {%0,%1,%2,%3};" \
        : "+f"((c)[0]), "+f"((c)[1]), "+f"((c)[2]), "+f"((c)[3]) \
        : "r"((a)[0]), "r"((a)[1]), "r"((a)[2]), "r"((a)[3]), "r"((b)[0]), "r"((b)[1]))

#define SWZ64(off)  ((off) ^ (((off) >> 3) & 0x30))
#define SWZ128(off) ((off) ^ (((off) >> 3) & 0x70))

__device__ __forceinline__ float ex2f(float x) {
    float y; asm("ex2.approx.ftz.f32 %0, %1;" : "=f"(y) : "f"(x)); return y;
}
__device__ __forceinline__ uint32_t pack_hf2(float a, float b) {
    __half2 h = __floats2half2_rn(a, b);
    return *(uint32_t*)&h;
}

// ---------------------------------------------------------------------------
// Preprocessing
// ---------------------------------------------------------------------------
__global__ __launch_bounds__(256) void split_kernel(
    const float* __restrict__ X, __half* __restrict__ hi,
    __half* __restrict__ lo, int n4)
{
    int i = blockIdx.x * blockDim.x + threadIdx.x;
    if (i >= n4) return;
    float4 v = ((const float4*)X)[i];
    __half h[4], l[4];
    float f[4] = {v.x, v.y, v.z, v.w};
    #pragma unroll
    for (int j = 0; j < 4; j++) {
        h[j] = __float2half_rn(f[j]);
        l[j] = __float2half_rn(f[j] - __half2float(h[j]));
    }
    ((uint2*)hi)[i] = *(uint2*)h;
    ((uint2*)lo)[i] = *(uint2*)l;
}

// W [K, N] fp32 -> T [N, K] fp16 hi only (transpose + quantize)
__global__ __launch_bounds__(256) void transpose_h(
    const float* __restrict__ W, __half* __restrict__ Th, int K, int N)
{
    __shared__ float tile[32][33];
    int tx = threadIdx.x & 31, ty = threadIdx.x >> 5;
    int k0 = blockIdx.y * 32, n0 = blockIdx.x * 32;
    #pragma unroll
    for (int i = 0; i < 32; i += 8)
        tile[ty + i][tx] = W[(size_t)(k0 + ty + i) * N + n0 + tx];
    __syncthreads();
    #pragma unroll
    for (int i = 0; i < 32; i += 8) {
        float v = tile[tx][ty + i];
        Th[(size_t)(n0 + ty + i) * K + k0 + tx] = __float2half_rn(v);
    }
}

// ---------------------------------------------------------------------------
// HMMA fp16 2-product GEMM (persistent CTAs): C = (Ahi+Alo)[M,K] @ Bh[N,K]^T
// CTA tile 128x128, BK=32, 3-stage cp.async, 2 CTAs/SM, tile loop per CTA.
// Stage (24KB): Ahi[0,8K) Alo[8K,16K) Bh[16K,24K)
// ---------------------------------------------------------------------------
#define GST 24576
#define GSMEM_TOTAL (3 * GST)

#define LOAD_STAGE(sidx, kc) do {                                              \
    uint32_t sb = sbase + (uint32_t)(sidx) * GST;                              \
    _Pragma("unroll")                                                          \
    for (int t_ = 0; t_ < 2; ++t_) {                                           \
        int v_ = tid + t_ * 256;                                               \
        int row_ = v_ >> 2, cb_ = v_ & 3;                                      \
        uint32_t sw_ = SWZ64((uint32_t)(row_ * 64 + cb_ * 16));                \
        size_t gA_ = (size_t)(rowBase + row_) * K + (kc) + cb_ * 8;            \
        size_t gB_ = (size_t)(colBase + row_) * K + (kc) + cb_ * 8;            \
        CPA16(sb + sw_,         (const char*)(Ahi + gA_));                     \
        CPA16(sb + 8192  + sw_, (const char*)(Alo + gA_));                     \
        CPA16(sb + 16384 + sw_, (const char*)(Bh + gB_));                      \
    }                                                                          \
} while (0)

template <bool SPLIT>
__global__ __launch_bounds__(256, 2) void gemm_mma(
    const __half* __restrict__ Ahi, const __half* __restrict__ Alo,
    const __half* __restrict__ Bh,
    float* __restrict__ C, __half* __restrict__ Chi,
    __half* __restrict__ Clo, int M, int N, int K)
{
    extern __shared__ char smem[];
    const uint32_t sbase = smem_u32(smem);
    const int tid  = threadIdx.x;
    const int lane = tid & 31;
    const int wid  = tid >> 5;
    const int wm = (wid & 3) * 32;
    const int wn = (wid >> 2) * 64;

    const int mi = lane >> 3;
    const uint32_t a_off = (uint32_t)((((mi & 1) * 8 + (lane & 7)) * 64) + (mi >> 1) * 16);
    const uint32_t b_off = (uint32_t)((((mi >> 1) * 8 + (lane & 7)) * 64) + (mi & 1) * 16);

    const int ntx = N / 128;
    const int ntiles = ntx * (M / 128);
    const int nk = K / 32;                 // 32

    for (int tIdx = blockIdx.x; tIdx < ntiles; tIdx += gridDim.x) {
        const int rowBase = (tIdx / ntx) * 128;
        const int colBase = (tIdx % ntx) * 128;

        float acc[2][8][4];
        #pragma unroll
        for (int i = 0; i < 2; i++)
            #pragma unroll
            for (int j = 0; j < 8; j++)
                #pragma unroll
                for (int q = 0; q < 4; q++) acc[i][j][q] = 0.f;

        __syncthreads();   // previous tile's smem reads complete before refill
        LOAD_STAGE(0, 0);  CP_COMMIT();
        LOAD_STAGE(1, 32); CP_COMMIT();

        int sidx = 0;
        for (int c = 0; c < nk; ++c) {
            if (c + 1 < nk) { CP_WAIT1(); } else { CP_WAIT0(); }
            __syncthreads();
            if (c + 2 < nk) {
                int ns = sidx + 2; if (ns >= 3) ns -= 3;
                LOAD_STAGE(ns, (c + 2) * 32);
                CP_COMMIT();
            }

            const uint32_t st = sbase + (uint32_t)sidx * GST;

            // hoist all A fragments for this chunk (both kb halves)
            uint32_t Ah[2][2][4], Al[2][2][4];
            #pragma unroll
            for (int kb2 = 0; kb2 < 2; kb2++)
                #pragma unroll
                for (int i = 0; i < 2; i++) {
                    uint32_t off = (uint32_t)((wm + i * 16) * 64 + kb2 * 32) + a_off;
                    LDSM_X4(Ah[kb2][i], st + SWZ64(off));
                    LDSM_X4(Al[kb2][i], st + 8192 + SWZ64(off));
                }

            // B fragments double-buffered across the flattened (kb, jp) loop
            uint32_t Bf[2][4];
            {
                uint32_t off = (uint32_t)(wn * 64) + b_off;   // kb=0, jp=0
                LDSM_X4(Bf[0], st + 16384 + SWZ64(off));
            }
            int bb = 0;
            #pragma unroll
            for (int it = 0; it < 8; it++) {            // it = kb*4 + jp
                const int kb = it >> 2, jp = it & 3;
                if (it + 1 < 8) {
                    const int nkb = (it + 1) >> 2, njp = (it + 1) & 3;
                    uint32_t off = (uint32_t)((wn + njp * 16) * 64 + nkb * 32) + b_off;
                    LDSM_X4(Bf[bb ^ 1], st + 16384 + SWZ64(off));
                }
                // 2-product: A-side exact, B-side fp16
                #pragma unroll
                for (int i = 0; i < 2; i++)
                    #pragma unroll
                    for (int jj = 0; jj < 2; jj++)
                        MMA16816(acc[i][jp * 2 + jj], Ah[kb][i], (&Bf[bb][jj * 2]));
                #pragma unroll
                for (int i = 0; i < 2; i++)
                    #pragma unroll
                    for (int jj = 0; jj < 2; jj++)
                        MMA16816(acc[i][jp * 2 + jj], Al[kb][i], (&Bf[bb][jj * 2]));
                bb ^= 1;
            }
            ++sidx; if (sidx >= 3) sidx = 0;
        }

        // SC2 folded into Q columns (SPLIT path only; colBase uniform per CTA)
        const float oscale = (SPLIT && colBase < DIM) ? SC2 : 1.0f;
        const bool  wrLo   = SPLIT && (colBase < DIM);   // lo only read for Q

        #pragma unroll
        for (int i = 0; i < 2; i++) {
            #pragma unroll
            for (int j = 0; j < 8; j++) {
                int r0 = rowBase + wm + i * 16 + (lane >> 2);
                int c0 = colBase + wn + j * 8 + (lane & 3) * 2;
                if (SPLIT) {
                    #pragma unroll
                    for (int hh = 0; hh < 2; hh++) {
                        float v0 = acc[i][j][hh * 2] * oscale, v1 = acc[i][j][hh * 2 + 1] * oscale;
                        __half2 h2 = __floats2half2_rn(v0, v1);
                        size_t idx = ((size_t)(r0 + hh * 8) * N + c0) >> 1;
                        ((uint32_t*)Chi)[idx] = *(uint32_t*)&h2;
                        if (wrLo) {
                            float l0 = v0 - __half2float(h2.x);
                            float l1 = v1 - __half2float(h2.y);
                            ((uint32_t*)Clo)[idx] = pack_hf2(l0, l1);
                        }
                    }
                } else {
                    *(float2*)&C[(size_t)r0 * N + c0]       = make_float2(acc[i][j][0], acc[i][j][1]);
                    *(float2*)&C[(size_t)(r0 + 8) * N + c0] = make_float2(acc[i][j][2], acc[i][j][3]);
                }
            }
        }
    }
}

// ---------------------------------------------------------------------------
// Flash attention, fp16. CTA = 128 q rows of one (b,h); 8 warps.
// QK: 2-product (Q exact, K hi). PV: 1-product (P fp16-hi, V hi) — P in [0,1],
// quantization error ~2^-12 relative, same magnitude as accepted V-hi error.
// 3-stage KV pipeline: stage 16KB (Khi|Vhi), 3 stages + Qhi/Qlo 32KB = 80KB.
// Non-persistent grid (512 CTAs) — persistence regressed here (R12).
// ---------------------------------------------------------------------------
#define FST     16384
#define F_KHI   0
#define F_VHI   8192
#define FQ_OFF  (3 * FST)
#define FSMEM_TOTAL (3 * FST + 32768)

#define FLOAD_KV(sidx, c0b) do {                                               \
    uint32_t sb = sbase + (uint32_t)(sidx) * FST;                              \
    _Pragma("unroll")                                                          \
    for (int t_ = 0; t_ < 2; ++t_) {                                           \
        int v_ = tid + t_ * 256;                                               \
        int row_ = v_ >> 3, ch_ = v_ & 7;                                      \
        uint32_t sw_ = SWZ128((uint32_t)(row_ * 128 + ch_ * 16));              \
        size_t base_ = ((size_t)(bS + (c0b) + row_) * 3) * DIM + hHD + ch_ * 8;\
        CPA16(sb + F_KHI + sw_, (const char*)(qh + base_ + DIM));              \
        CPA16(sb + F_VHI + sw_, (const char*)(qh + base_ + 2 * DIM));          \
    }                                                                          \
} while (0)

__global__ __launch_bounds__(256, 2) void flash_mma(
    const __half* __restrict__ qh, const __half* __restrict__ ql,
    __half* __restrict__ Ahi, __half* __restrict__ Alo)
{
    extern __shared__ char smem[];
    const uint32_t sbase = smem_u32(smem);
    const int tid  = threadIdx.x;
    const int lane = tid & 31;
    const int wid  = tid >> 5;
    const int wrow = wid * 16;
    const int h  = blockIdx.y;
    const int b  = blockIdx.z;
    const int q0 = blockIdx.x * 128;
    const int bS  = b * SEQ;
    const int hHD = h * HD;

    const int mi = lane >> 3;
    const uint32_t a_row = (mi & 1) * 8 + (lane & 7);
    const uint32_t a_ch  = (mi >> 1) * 16;
    const uint32_t b_row = (mi >> 1) * 8 + (lane & 7);
    const uint32_t b_ch  = (mi & 1) * 16;

    // Q tile (hi+lo) + KV stages 0,1 (two commit groups in flight)
    {
        #pragma unroll
        for (int t_ = 0; t_ < 4; ++t_) {
            int v_ = tid + t_ * 256;
            int row_ = v_ >> 3, ch_ = v_ & 7;
            uint32_t sw_ = SWZ128((uint32_t)(row_ * 128 + ch_ * 16));
            size_t base_ = ((size_t)(bS + q0 + row_) * 3) * DIM + hHD + ch_ * 8;
            CPA16(sbase + FQ_OFF + sw_,         (const char*)(qh + base_));
            CPA16(sbase + FQ_OFF + 16384 + sw_, (const char*)(ql + base_));
        }
        FLOAD_KV(0, 0);
        CP_COMMIT();
        FLOAD_KV(1, 64);
        CP_COMMIT();
    }

    float S[8][4];
    float O[8][4];
    #pragma unroll
    for (int j = 0; j < 8; j++)
        #pragma unroll
        for (int q = 0; q < 4; q++) O[j][q] = 0.f;
    float mA = -1e30f, mB = -1e30f, lA = 0.f, lB = 0.f;

    const int ntiles = SEQ / 64;   // 32
    int sidx = 0;                  // stage of tile tI (mod 3)

    for (int tI = 0; tI < ntiles; ++tI) {
        if (tI + 1 < ntiles) { CP_WAIT1(); } else { CP_WAIT0(); }
        __syncthreads();           // all warps done reading stage (tI+2)%3
        if (tI + 2 < ntiles) {
            int ns = sidx + 2; if (ns >= 3) ns -= 3;
            FLOAD_KV(ns, (tI + 2) * 64);
            CP_COMMIT();
        }

        const uint32_t st = sbase + (uint32_t)sidx * FST;

        // ---- S = Q K^T (2-product: Q exact, K hi-only) ----
        #pragma unroll
        for (int nb = 0; nb < 8; nb++)
            #pragma unroll
            for (int q = 0; q < 4; q++) S[nb][q] = 0.f;

        uint32_t Kh[2][4];
        {
            uint32_t koff = SWZ128((uint32_t)(b_row * 128) + b_ch);   // dks=0, nbp=0
            LDSM_X4(Kh[0], st + F_KHI + koff);
        }
        uint32_t qhi[4], qlo[4];
        int kb = 0;
        #pragma unroll
        for (int it = 0; it < 16; it++) {           // it = dks*4 + nbp
            const int dks = it >> 2, nbp = it & 3;
            if (nbp == 0) {
                uint32_t qoff = SWZ128((uint32_t)((wrow + a_row) * 128 + dks * 32) + a_ch);
                LDSM_X4(qhi, sbase + FQ_OFF + qoff);
                LDSM_X4(qlo, sbase + FQ_OFF + 16384 + qoff);
            }
            if (it + 1 < 16) {
                const int nd = (it + 1) >> 2, nn = (it + 1) & 3;
                uint32_t koff = SWZ128((uint32_t)((nn * 16 + b_row) * 128 + nd * 32) + b_ch);
                LDSM_X4(Kh[kb ^ 1], st + F_KHI + koff);
            }
            float* s0 = S[nbp * 2 + 0];
            float* s1 = S[nbp * 2 + 1];
            MMA16816(s0, qhi, (&Kh[kb][0]));
            MMA16816(s1, qhi, (&Kh[kb][2]));
            MMA16816(s0, qlo, (&Kh[kb][0]));
            MMA16816(s1, qlo, (&Kh[kb][2]));
            kb ^= 1;
        }

        // ---- row max + O rescale ----
        float mxA = -1e30f, mxB = -1e30f;
        #pragma unroll
        for (int nb = 0; nb < 8; nb++) {
            mxA = fmaxf(mxA, fmaxf(S[nb][0], S[nb][1]));
            mxB = fmaxf(mxB, fmaxf(S[nb][2], S[nb][3]));
        }
        #pragma unroll
        for (int d = 1; d <= 2; d <<= 1) {
            mxA = fmaxf(mxA, __shfl_xor_sync(0xffffffffu, mxA, d));
            mxB = fmaxf(mxB, __shfl_xor_sync(0xffffffffu, mxB, d));
        }
        float mAn = fmaxf(mA, mxA), mBn = fmaxf(mB, mxB);
        float fA = ex2f(mA - mAn),  fB = ex2f(mB - mBn);
        #pragma unroll
        for (int j = 0; j < 8; j++) {
            O[j][0] *= fA; O[j][1] *= fA; O[j][2] *= fB; O[j][3] *= fB;
        }

        // ---- PV (1-product: P fp16-hi, V hi; exp interleaved) ----
        float sA = 0.f, sB = 0.f;
        uint32_t Vh[2][4];
        {
            uint32_t voff = SWZ128((uint32_t)(a_row * 128) + a_ch);   // ks=0, dg=0
            LDSM_X4T(Vh[0], st + F_VHI + voff);
        }
        uint32_t ph[4];
        int vb = 0;
        #pragma unroll
        for (int it = 0; it < 16; it++) {           // it = ks*4 + dg
            const int ks = it >> 2, dg = it & 3;
            if (dg == 0) {
                float pv[2][4];
                #pragma unroll
                for (int jj = 0; jj < 2; jj++) {
                    const float* sv = S[ks * 2 + jj];
                    pv[jj][0] = ex2f(sv[0] - mAn);
                    pv[jj][1] = ex2f(sv[1] - mAn);
                    pv[jj][2] = ex2f(sv[2] - mBn);
                    pv[jj][3] = ex2f(sv[3] - mBn);
                    sA += pv[jj][0] + pv[jj][1];
                    sB += pv[jj][2] + pv[jj][3];
                }
                #pragma unroll
                for (int u = 0; u < 4; u++) {
                    const float* sv = pv[u >> 1];
                    ph[u] = pack_hf2(sv[(u & 1) * 2], sv[(u & 1) * 2 + 1]);
                }
            }
            if (it + 1 < 16) {
                const int nks = (it + 1) >> 2, ndg = (it + 1) & 3;
                uint32_t voff = SWZ128((uint32_t)((nks * 16 + a_row) * 128 + ndg * 32) + a_ch);
                LDSM_X4T(Vh[vb ^ 1], st + F_VHI + voff);
            }
            float* o0 = O[dg * 2 + 0];
            float* o1 = O[dg * 2 + 1];
            MMA16816(o0, ph, (&Vh[vb][0]));
            MMA16816(o1, ph, (&Vh[vb][2]));
            vb ^= 1;
        }
        #pragma unroll
        for (int d = 1; d <= 2; d <<= 1) {
            sA += __shfl_xor_sync(0xffffffffu, sA, d);
            sB += __shfl_xor_sync(0xffffffffu, sB, d);
        }
        lA = lA * fA + sA;  lB = lB * fB + sB;
        mA = mAn;           mB = mBn;

        ++sidx; if (sidx >= 3) sidx = 0;
    }

    // ---- epilogue: normalize, split to fp16 hi/lo, store ----
    float invA = 1.f / lA, invB = 1.f / lB;
    int rA = bS + q0 + wrow + (lane >> 2);
    int rB = rA + 8;
    #pragma unroll
    for (int j = 0; j < 8; j++) {
        int d0 = j * 8 + (lane & 3) * 2;
        float a0 = O[j][0] * invA, a1 = O[j][1] * invA;
        float b0 = O[j][2] * invB, b1 = O[j][3] * invB;
        __half2 hA = __floats2half2_rn(a0, a1);
        __half2 hB = __floats2half2_rn(b0, b1);
        size_t iA = ((size_t)rA * DIM + hHD + d0) >> 1;
        size_t iB = ((size_t)rB * DIM + hHD + d0) >> 1;
        ((uint32_t*)Ahi)[iA] = *(uint32_t*)&hA;
        ((uint32_t*)Ahi)[iB] = *(uint32_t*)&hB;
        ((uint32_t*)Alo)[iA] = pack_hf2(a0 - __half2float(hA.x), a1 - __half2float(hA.y));
        ((uint32_t*)Alo)[iB] = pack_hf2(b0 - __half2float(hB.x), b1 - __half2float(hB.y));
    }
}

// ---------------------------------------------------------------------------
extern "C" void kernel_launch(void* const* d_in, const int* in_sizes, int n_in,
                              void* d_out, int out_size)
{
    const float* x     = (const float*)d_in[0];
    const float* Wqkv  = (const float*)d_in[1];
    const float* Wproj = (const float*)d_in[2];
    float* out = (float*)d_out;

    __half *xhi, *xlo, *qh, *ql, *ahi, *alo, *wqh, *wph;
    cudaGetSymbolAddress((void**)&xhi, g_xhi);
    cudaGetSymbolAddress((void**)&xlo, g_xlo);
    cudaGetSymbolAddress((void**)&qh,  g_qh);
    cudaGetSymbolAddress((void**)&ql,  g_ql);
    cudaGetSymbolAddress((void**)&ahi, g_ahi);
    cudaGetSymbolAddress((void**)&alo, g_alo);
    cudaGetSymbolAddress((void**)&wqh, g_wqh);
    cudaGetSymbolAddress((void**)&wph, g_wph);

    const int M = BATCH * SEQ;          // 4096

    cudaFuncSetAttribute(gemm_mma<true>,  cudaFuncAttributeMaxDynamicSharedMemorySize, GSMEM_TOTAL);
    cudaFuncSetAttribute(gemm_mma<false>, cudaFuncAttributeMaxDynamicSharedMemorySize, GSMEM_TOTAL);
    cudaFuncSetAttribute(flash_mma,       cudaFuncAttributeMaxDynamicSharedMemorySize, FSMEM_TOTAL);

    // 0) splits / weight transposes (hi only)
    split_kernel<<<(M * DIM / 4 + 255) / 256, 256>>>(x, xhi, xlo, M * DIM / 4);
    {
        dim3 g1(3 * DIM / 32, DIM / 32);
        transpose_h<<<g1, 256>>>(Wqkv, wqh, DIM, 3 * DIM);
        dim3 g2(DIM / 32, DIM / 32);
        transpose_h<<<g2, 256>>>(Wproj, wph, DIM, DIM);
    }

    // 1) qkv = x @ Wqkv -> fp16 hi/lo (Q pre-scaled by SC2), persistent grid
    {
        int tiles = (3 * DIM / 128) * (M / 128);       // 768
        int grid  = tiles < NSLOTS ? tiles : NSLOTS;
        gemm_mma<true><<<grid, 256, GSMEM_TOTAL>>>(xhi, xlo, wqh,
                                                   nullptr, qh, ql, M, 3 * DIM, DIM);
    }

    // 2) flash attention -> fp16 hi/lo, non-persistent grid
    {
        dim3 grid(SEQ / 128, NHEAD, BATCH);
        flash_mma<<<grid, 256, FSMEM_TOTAL>>>(qh, ql, ahi, alo);
    }

    // 3) out = attn @ Wproj (fp32 out), persistent grid
    {
        int tiles = (DIM / 128) * (M / 128);           // 256
        int grid  = tiles < NSLOTS ? tiles : NSLOTS;
        gemm_mma<false><<<grid, 256, GSMEM_TOTAL>>>(ahi, alo, wph,
                                                    out, nullptr, nullptr, M, DIM, DIM);
    }
}

// round 15
// speedup vs baseline: 1.2454x; 1.0859x over previous
#include <cuda_runtime.h>
#include <cuda_fp16.h>
#include <cstdint>
#include <cstddef>

#define BATCH 2
#define SEQ   2048
#define DIM   1024
#define NHEAD 16
#define HD    64
// SCALE * log2(e): logits kept in base-2 domain (folded into Q at QKV epilogue)
#define SC2   0.18033688011112042f

#define NSLOTS 296   // 148 SMs x 2 CTAs/SM

// ---------------------------------------------------------------------------
// Scratch (allocation-free rule: __device__ globals) — fp16 scheme
// ---------------------------------------------------------------------------
__device__ __half g_xhi[(size_t)BATCH * SEQ * DIM];
__device__ __half g_xlo[(size_t)BATCH * SEQ * DIM];
__device__ __half g_qh [(size_t)BATCH * SEQ * 3 * DIM];   // qkv hi (Q pre-scaled)
__device__ __half g_ahi[(size_t)BATCH * SEQ * DIM];       // attn hi
__device__ __half g_alo[(size_t)BATCH * SEQ * DIM];       // attn lo
__device__ __half g_wqh[(size_t)3 * DIM * DIM];           // [3072,1024] K-major, hi only
__device__ __half g_wph[(size_t)DIM * DIM];               // [1024,1024] K-major, hi only

// ---------------------------------------------------------------------------
// Portable PTX helpers
// ---------------------------------------------------------------------------
__device__ __forceinline__ uint32_t smem_u32(const void* p) {
    uint32_t a;
    asm("{ .reg .u64 t; cvta.to.shared.u64 t, %1; cvt.u32.u64 %0, t; }" : "=r"(a) : "l"(p));
    return a;
}
#define CPA16(dst, src) \
    asm volatile("cp.async.cg.shared.global [%0], [%1], 16;" :: "r"(dst), "l"(src) : "memory")
#define CP_COMMIT() asm volatile("cp.async.commit_group;" ::: "memory")
#define CP_WAIT0()  asm volatile("cp.async.wait_group 0;" ::: "memory")
#define CP_WAIT1()  asm volatile("cp.async.wait_group 1;" ::: "memory")

#define LDSM_X4(r, addr) \
    asm volatile("ldmatrix.sync.aligned.m8n8.x4.shared.b16 {%0,%1,%2,%3}, [%4];" \
        : "=r"((r)[0]), "=r"((r)[1]), "=r"((r)[2]), "=r"((r)[3]) : "r"(addr))
#define LDSM_X4T(r, addr) \
    asm volatile("ldmatrix.sync.aligned.m8n8.x4.trans.shared.b16 {%0,%1,%2,%3}, [%4];" \
        : "=r"((r)[0]), "=r"((r)[1]), "=r"((r)[2]), "=r"((r)[3]) : "r"(addr))

// fp16 HMMA, fp32 accumulate
#define MMA16816(c, a, b) \
    asm volatile("mma.sync.aligned.m16n8k16.row.col.f32.f16.f16.f32 " \
        "{%0,%1,%2,%3}, {%4,%5,%6,%7}, {%8,%9}, {%0,%1,%2,%3};" \
        : "+f"((c)[0]), "+f"((c)[1]), "+f"((c)[2]), "+f"((c)[3]) \
        : "r"((a)[0]), "r"((a)[1]), "r"((a)[2]), "r"((a)[3]), "r"((b)[0]), "r"((b)[1]))

#define SWZ64(off)  ((off) ^ (((off) >> 3) & 0x30))
#define SWZ128(off) ((off) ^ (((off) >> 3) & 0x70))

__device__ __forceinline__ float ex2f(float x) {
    float y; asm("ex2.approx.ftz.f32 %0, %1;" : "=f"(y) : "f"(x)); return y;
}
__device__ __forceinline__ uint32_t pack_hf2(float a, float b) {
    __half2 h = __floats2half2_rn(a, b);
    return *(uint32_t*)&h;
}

// ---------------------------------------------------------------------------
// Preprocessing
// ---------------------------------------------------------------------------
__global__ __launch_bounds__(256) void split_kernel(
    const float* __restrict__ X, __half* __restrict__ hi,
    __half* __restrict__ lo, int n4)
{
    int i = blockIdx.x * blockDim.x + threadIdx.x;
    if (i >= n4) return;
    float4 v = ((const float4*)X)[i];
    __half h[4], l[4];
    float f[4] = {v.x, v.y, v.z, v.w};
    #pragma unroll
    for (int j = 0; j < 4; j++) {
        h[j] = __float2half_rn(f[j]);
        l[j] = __float2half_rn(f[j] - __half2float(h[j]));
    }
    ((uint2*)hi)[i] = *(uint2*)h;
    ((uint2*)lo)[i] = *(uint2*)l;
}

// W [K, N] fp32 -> T [N, K] fp16 hi only (transpose + quantize)
__global__ __launch_bounds__(256) void transpose_h(
    const float* __restrict__ W, __half* __restrict__ Th, int K, int N)
{
    __shared__ float tile[32][33];
    int tx = threadIdx.x & 31, ty = threadIdx.x >> 5;
    int k0 = blockIdx.y * 32, n0 = blockIdx.x * 32;
    #pragma unroll
    for (int i = 0; i < 32; i += 8)
        tile[ty + i][tx] = W[(size_t)(k0 + ty + i) * N + n0 + tx];
    __syncthreads();
    #pragma unroll
    for (int i = 0; i < 32; i += 8) {
        float v = tile[tx][ty + i];
        Th[(size_t)(n0 + ty + i) * K + k0 + tx] = __float2half_rn(v);
    }
}

// ---------------------------------------------------------------------------
// HMMA fp16 2-product GEMM (persistent CTAs): C = (Ahi+Alo)[M,K] @ Bh[N,K]^T
// CTA tile 128x128, BK=32, 3-stage cp.async, 2 CTAs/SM, tile loop per CTA.
// Stage (24KB): Ahi[0,8K) Alo[8K,16K) Bh[16K,24K)
// SPLIT epilogue: fp16-hi only (no lo consumer), Q columns scaled by SC2.
// ---------------------------------------------------------------------------
#define GST 24576
#define GSMEM_TOTAL (3 * GST)

#define LOAD_STAGE(sidx, kc) do {                                              \
    uint32_t sb = sbase + (uint32_t)(sidx) * GST;                              \
    _Pragma("unroll")                                                          \
    for (int t_ = 0; t_ < 2; ++t_) {                                           \
        int v_ = tid + t_ * 256;                                               \
        int row_ = v_ >> 2, cb_ = v_ & 3;                                      \
        uint32_t sw_ = SWZ64((uint32_t)(row_ * 64 + cb_ * 16));                \
        size_t gA_ = (size_t)(rowBase + row_) * K + (kc) + cb_ * 8;            \
        size_t gB_ = (size_t)(colBase + row_) * K + (kc) + cb_ * 8;            \
        CPA16(sb + sw_,         (const char*)(Ahi + gA_));                     \
        CPA16(sb + 8192  + sw_, (const char*)(Alo + gA_));                     \
        CPA16(sb + 16384 + sw_, (const char*)(Bh + gB_));                      \
    }                                                                          \
} while (0)

template <bool SPLIT>
__global__ __launch_bounds__(256, 2) void gemm_mma(
    const __half* __restrict__ Ahi, const __half* __restrict__ Alo,
    const __half* __restrict__ Bh,
    float* __restrict__ C, __half* __restrict__ Chi,
    int M, int N, int K)
{
    extern __shared__ char smem[];
    const uint32_t sbase = smem_u32(smem);
    const int tid  = threadIdx.x;
    const int lane = tid & 31;
    const int wid  = tid >> 5;
    const int wm = (wid & 3) * 32;
    const int wn = (wid >> 2) * 64;

    const int mi = lane >> 3;
    const uint32_t a_off = (uint32_t)((((mi & 1) * 8 + (lane & 7)) * 64) + (mi >> 1) * 16);
    const uint32_t b_off = (uint32_t)((((mi >> 1) * 8 + (lane & 7)) * 64) + (mi & 1) * 16);

    const int ntx = N / 128;
    const int ntiles = ntx * (M / 128);
    const int nk = K / 32;                 // 32

    for (int tIdx = blockIdx.x; tIdx < ntiles; tIdx += gridDim.x) {
        const int rowBase = (tIdx / ntx) * 128;
        const int colBase = (tIdx % ntx) * 128;

        float acc[2][8][4];
        #pragma unroll
        for (int i = 0; i < 2; i++)
            #pragma unroll
            for (int j = 0; j < 8; j++)
                #pragma unroll
                for (int q = 0; q < 4; q++) acc[i][j][q] = 0.f;

        __syncthreads();   // previous tile's smem reads complete before refill
        LOAD_STAGE(0, 0);  CP_COMMIT();
        LOAD_STAGE(1, 32); CP_COMMIT();

        int sidx = 0;
        for (int c = 0; c < nk; ++c) {
            if (c + 1 < nk) { CP_WAIT1(); } else { CP_WAIT0(); }
            __syncthreads();
            if (c + 2 < nk) {
                int ns = sidx + 2; if (ns >= 3) ns -= 3;
                LOAD_STAGE(ns, (c + 2) * 32);
                CP_COMMIT();
            }

            const uint32_t st = sbase + (uint32_t)sidx * GST;

            // hoist all A fragments for this chunk (both kb halves)
            uint32_t Ah[2][2][4], Al[2][2][4];
            #pragma unroll
            for (int kb2 = 0; kb2 < 2; kb2++)
                #pragma unroll
                for (int i = 0; i < 2; i++) {
                    uint32_t off = (uint32_t)((wm + i * 16) * 64 + kb2 * 32) + a_off;
                    LDSM_X4(Ah[kb2][i], st + SWZ64(off));
                    LDSM_X4(Al[kb2][i], st + 8192 + SWZ64(off));
                }

            // B fragments double-buffered across the flattened (kb, jp) loop
            uint32_t Bf[2][4];
            {
                uint32_t off = (uint32_t)(wn * 64) + b_off;   // kb=0, jp=0
                LDSM_X4(Bf[0], st + 16384 + SWZ64(off));
            }
            int bb = 0;
            #pragma unroll
            for (int it = 0; it < 8; it++) {            // it = kb*4 + jp
                const int kb = it >> 2, jp = it & 3;
                if (it + 1 < 8) {
                    const int nkb = (it + 1) >> 2, njp = (it + 1) & 3;
                    uint32_t off = (uint32_t)((wn + njp * 16) * 64 + nkb * 32) + b_off;
                    LDSM_X4(Bf[bb ^ 1], st + 16384 + SWZ64(off));
                }
                // 2-product: A-side exact, B-side fp16
                #pragma unroll
                for (int i = 0; i < 2; i++)
                    #pragma unroll
                    for (int jj = 0; jj < 2; jj++)
                        MMA16816(acc[i][jp * 2 + jj], Ah[kb][i], (&Bf[bb][jj * 2]));
                #pragma unroll
                for (int i = 0; i < 2; i++)
                    #pragma unroll
                    for (int jj = 0; jj < 2; jj++)
                        MMA16816(acc[i][jp * 2 + jj], Al[kb][i], (&Bf[bb][jj * 2]));
                bb ^= 1;
            }
            ++sidx; if (sidx >= 3) sidx = 0;
        }

        // SC2 folded into Q columns (SPLIT path only; colBase uniform per CTA)
        const float oscale = (SPLIT && colBase < DIM) ? SC2 : 1.0f;

        #pragma unroll
        for (int i = 0; i < 2; i++) {
            #pragma unroll
            for (int j = 0; j < 8; j++) {
                int r0 = rowBase + wm + i * 16 + (lane >> 2);
                int c0 = colBase + wn + j * 8 + (lane & 3) * 2;
                if (SPLIT) {
                    #pragma unroll
                    for (int hh = 0; hh < 2; hh++) {
                        float v0 = acc[i][j][hh * 2] * oscale, v1 = acc[i][j][hh * 2 + 1] * oscale;
                        size_t idx = ((size_t)(r0 + hh * 8) * N + c0) >> 1;
                        ((uint32_t*)Chi)[idx] = pack_hf2(v0, v1);
                    }
                } else {
                    *(float2*)&C[(size_t)r0 * N + c0]       = make_float2(acc[i][j][0], acc[i][j][1]);
                    *(float2*)&C[(size_t)(r0 + 8) * N + c0] = make_float2(acc[i][j][2], acc[i][j][3]);
                }
            }
        }
    }
}

// ---------------------------------------------------------------------------
// Flash attention, fp16. CTA = 128 q rows of one (b,h); 8 warps.
// QK: 1-product (Q hi, K hi). PV: 1-product (P fp16-hi, V hi).
// 3-stage KV pipeline: stage 16KB (Khi|Vhi), 3 stages + Qhi 16KB = 64KB.
// Non-persistent grid (512 CTAs).
// ---------------------------------------------------------------------------
#define FST     16384
#define F_KHI   0
#define F_VHI   8192
#define FQ_OFF  (3 * FST)
#define FSMEM_TOTAL (3 * FST + 16384)

#define FLOAD_KV(sidx, c0b) do {                                               \
    uint32_t sb = sbase + (uint32_t)(sidx) * FST;                              \
    _Pragma("unroll")                                                          \
    for (int t_ = 0; t_ < 2; ++t_) {                                           \
        int v_ = tid + t_ * 256;                                               \
        int row_ = v_ >> 3, ch_ = v_ & 7;                                      \
        uint32_t sw_ = SWZ128((uint32_t)(row_ * 128 + ch_ * 16));              \
        size_t base_ = ((size_t)(bS + (c0b) + row_) * 3) * DIM + hHD + ch_ * 8;\
        CPA16(sb + F_KHI + sw_, (const char*)(qh + base_ + DIM));              \
        CPA16(sb + F_VHI + sw_, (const char*)(qh + base_ + 2 * DIM));          \
    }                                                                          \
} while (0)

__global__ __launch_bounds__(256, 2) void flash_mma(
    const __half* __restrict__ qh,
    __half* __restrict__ Ahi, __half* __restrict__ Alo)
{
    extern __shared__ char smem[];
    const uint32_t sbase = smem_u32(smem);
    const int tid  = threadIdx.x;
    const int lane = tid & 31;
    const int wid  = tid >> 5;
    const int wrow = wid * 16;
    const int h  = blockIdx.y;
    const int b  = blockIdx.z;
    const int q0 = blockIdx.x * 128;
    const int bS  = b * SEQ;
    const int hHD = h * HD;

    const int mi = lane >> 3;
    const uint32_t a_row = (mi & 1) * 8 + (lane & 7);
    const uint32_t a_ch  = (mi >> 1) * 16;
    const uint32_t b_row = (mi >> 1) * 8 + (lane & 7);
    const uint32_t b_ch  = (mi & 1) * 16;

    // Q tile (hi only) + KV stages 0,1 (two commit groups in flight)
    {
        #pragma unroll
        for (int t_ = 0; t_ < 4; ++t_) {
            int v_ = tid + t_ * 256;
            int row_ = v_ >> 3, ch_ = v_ & 7;
            uint32_t sw_ = SWZ128((uint32_t)(row_ * 128 + ch_ * 16));
            size_t base_ = ((size_t)(bS + q0 + row_) * 3) * DIM + hHD + ch_ * 8;
            CPA16(sbase + FQ_OFF + sw_, (const char*)(qh + base_));
        }
        FLOAD_KV(0, 0);
        CP_COMMIT();
        FLOAD_KV(1, 64);
        CP_COMMIT();
    }

    float S[8][4];
    float O[8][4];
    #pragma unroll
    for (int j = 0; j < 8; j++)
        #pragma unroll
        for (int q = 0; q < 4; q++) O[j][q] = 0.f;
    float mA = -1e30f, mB = -1e30f, lA = 0.f, lB = 0.f;

    const int ntiles = SEQ / 64;   // 32
    int sidx = 0;                  // stage of tile tI (mod 3)

    for (int tI = 0; tI < ntiles; ++tI) {
        if (tI + 1 < ntiles) { CP_WAIT1(); } else { CP_WAIT0(); }
        __syncthreads();           // all warps done reading stage (tI+2)%3
        if (tI + 2 < ntiles) {
            int ns = sidx + 2; if (ns >= 3) ns -= 3;
            FLOAD_KV(ns, (tI + 2) * 64);
            CP_COMMIT();
        }

        const uint32_t st = sbase + (uint32_t)sidx * FST;

        // ---- S = Q K^T (1-product: Q hi, K hi) ----
        #pragma unroll
        for (int nb = 0; nb < 8; nb++)
            #pragma unroll
            for (int q = 0; q < 4; q++) S[nb][q] = 0.f;

        uint32_t Kh[2][4];
        {
            uint32_t koff = SWZ128((uint32_t)(b_row * 128) + b_ch);   // dks=0, nbp=0
            LDSM_X4(Kh[0], st + F_KHI + koff);
        }
        uint32_t qhi[4];
        int kb = 0;
        #pragma unroll
        for (int it = 0; it < 16; it++) {           // it = dks*4 + nbp
            const int dks = it >> 2, nbp = it & 3;
            if (nbp == 0) {
                uint32_t qoff = SWZ128((uint32_t)((wrow + a_row) * 128 + dks * 32) + a_ch);
                LDSM_X4(qhi, sbase + FQ_OFF + qoff);
            }
            if (it + 1 < 16) {
                const int nd = (it + 1) >> 2, nn = (it + 1) & 3;
                uint32_t koff = SWZ128((uint32_t)((nn * 16 + b_row) * 128 + nd * 32) + b_ch);
                LDSM_X4(Kh[kb ^ 1], st + F_KHI + koff);
            }
            float* s0 = S[nbp * 2 + 0];
            float* s1 = S[nbp * 2 + 1];
            MMA16816(s0, qhi, (&Kh[kb][0]));
            MMA16816(s1, qhi, (&Kh[kb][2]));
            kb ^= 1;
        }

        // ---- row max + O rescale ----
        float mxA = -1e30f, mxB = -1e30f;
        #pragma unroll
        for (int nb = 0; nb < 8; nb++) {
            mxA = fmaxf(mxA, fmaxf(S[nb][0], S[nb][1]));
            mxB = fmaxf(mxB, fmaxf(S[nb][2], S[nb][3]));
        }
        #pragma unroll
        for (int d = 1; d <= 2; d <<= 1) {
            mxA = fmaxf(mxA, __shfl_xor_sync(0xffffffffu, mxA, d));
            mxB = fmaxf(mxB, __shfl_xor_sync(0xffffffffu, mxB, d));
        }
        float mAn = fmaxf(mA, mxA), mBn = fmaxf(mB, mxB);
        float fA = ex2f(mA - mAn),  fB = ex2f(mB - mBn);
        #pragma unroll
        for (int j = 0; j < 8; j++) {
            O[j][0] *= fA; O[j][1] *= fA; O[j][2] *= fB; O[j][3] *= fB;
        }

        // ---- PV (1-product: P fp16-hi, V hi; exp interleaved) ----
        float sA = 0.f, sB = 0.f;
        uint32_t Vh[2][4];
        {
            uint32_t voff = SWZ128((uint32_t)(a_row * 128) + a_ch);   // ks=0, dg=0
            LDSM_X4T(Vh[0], st + F_VHI + voff);
        }
        uint32_t ph[4];
        int vb = 0;
        #pragma unroll
        for (int it = 0; it < 16; it++) {           // it = ks*4 + dg
            const int ks = it >> 2, dg = it & 3;
            if (dg == 0) {
                float pv[2][4];
                #pragma unroll
                for (int jj = 0; jj < 2; jj++) {
                    const float* sv = S[ks * 2 + jj];
                    pv[jj][0] = ex2f(sv[0] - mAn);
                    pv[jj][1] = ex2f(sv[1] - mAn);
                    pv[jj][2] = ex2f(sv[2] - mBn);
                    pv[jj][3] = ex2f(sv[3] - mBn);
                    sA += pv[jj][0] + pv[jj][1];
                    sB += pv[jj][2] + pv[jj][3];
                }
                #pragma unroll
                for (int u = 0; u < 4; u++) {
                    const float* sv = pv[u >> 1];
                    ph[u] = pack_hf2(sv[(u & 1) * 2], sv[(u & 1) * 2 + 1]);
                }
            }
            if (it + 1 < 16) {
                const int nks = (it + 1) >> 2, ndg = (it + 1) & 3;
                uint32_t voff = SWZ128((uint32_t)((nks * 16 + a_row) * 128 + ndg * 32) + a_ch);
                LDSM_X4T(Vh[vb ^ 1], st + F_VHI + voff);
            }
            float* o0 = O[dg * 2 + 0];
            float* o1 = O[dg * 2 + 1];
            MMA16816(o0, ph, (&Vh[vb][0]));
            MMA16816(o1, ph, (&Vh[vb][2]));
            vb ^= 1;
        }
        #pragma unroll
        for (int d = 1; d <= 2; d <<= 1) {
            sA += __shfl_xor_sync(0xffffffffu, sA, d);
            sB += __shfl_xor_sync(0xffffffffu, sB, d);
        }
        lA = lA * fA + sA;  lB = lB * fB + sB;
        mA = mAn;           mB = mBn;

        ++sidx; if (sidx >= 3) sidx = 0;
    }

    // ---- epilogue: normalize, split to fp16 hi/lo, store ----
    float invA = 1.f / lA, invB = 1.f / lB;
    int rA = bS + q0 + wrow + (lane >> 2);
    int rB = rA + 8;
    #pragma unroll
    for (int j = 0; j < 8; j++) {
        int d0 = j * 8 + (lane & 3) * 2;
        float a0 = O[j][0] * invA, a1 = O[j][1] * invA;
        float b0 = O[j][2] * invB, b1 = O[j][3] * invB;
        __half2 hA = __floats2half2_rn(a0, a1);
        __half2 hB = __floats2half2_rn(b0, b1);
        size_t iA = ((size_t)rA * DIM + hHD + d0) >> 1;
        size_t iB = ((size_t)rB * DIM + hHD + d0) >> 1;
        ((uint32_t*)Ahi)[iA] = *(uint32_t*)&hA;
        ((uint32_t*)Ahi)[iB] = *(uint32_t*)&hB;
        ((uint32_t*)Alo)[iA] = pack_hf2(a0 - __half2float(hA.x), a1 - __half2float(hA.y));
        ((uint32_t*)Alo)[iB] = pack_hf2(b0 - __half2float(hB.x), b1 - __half2float(hB.y));
    }
}

// ---------------------------------------------------------------------------
extern "C" void kernel_launch(void* const* d_in, const int* in_sizes, int n_in,
                              void* d_out, int out_size)
{
    const float* x     = (const float*)d_in[0];
    const float* Wqkv  = (const float*)d_in[1];
    const float* Wproj = (const float*)d_in[2];
    float* out = (float*)d_out;

    __half *xhi, *xlo, *qh, *ahi, *alo, *wqh, *wph;
    cudaGetSymbolAddress((void**)&xhi, g_xhi);
    cudaGetSymbolAddress((void**)&xlo, g_xlo);
    cudaGetSymbolAddress((void**)&qh,  g_qh);
    cudaGetSymbolAddress((void**)&ahi, g_ahi);
    cudaGetSymbolAddress((void**)&alo, g_alo);
    cudaGetSymbolAddress((void**)&wqh, g_wqh);
    cudaGetSymbolAddress((void**)&wph, g_wph);

    const int M = BATCH * SEQ;          // 4096

    cudaFuncSetAttribute(gemm_mma<true>,  cudaFuncAttributeMaxDynamicSharedMemorySize, GSMEM_TOTAL);
    cudaFuncSetAttribute(gemm_mma<false>, cudaFuncAttributeMaxDynamicSharedMemorySize, GSMEM_TOTAL);
    cudaFuncSetAttribute(flash_mma,       cudaFuncAttributeMaxDynamicSharedMemorySize, FSMEM_TOTAL);

    // 0) splits / weight transposes (hi only)
    split_kernel<<<(M * DIM / 4 + 255) / 256, 256>>>(x, xhi, xlo, M * DIM / 4);
    {
        dim3 g1(3 * DIM / 32, DIM / 32);
        transpose_h<<<g1, 256>>>(Wqkv, wqh, DIM, 3 * DIM);
        dim3 g2(DIM / 32, DIM / 32);
        transpose_h<<<g2, 256>>>(Wproj, wph, DIM, DIM);
    }

    // 1) qkv = x @ Wqkv -> fp16 hi (Q pre-scaled by SC2), persistent grid
    {
        int tiles = (3 * DIM / 128) * (M / 128);       // 768
        int grid  = tiles < NSLOTS ? tiles : NSLOTS;
        gemm_mma<true><<<grid, 256, GSMEM_TOTAL>>>(xhi, xlo, wqh,
                                                   nullptr, qh, M, 3 * DIM, DIM);
    }

    // 2) flash attention -> fp16 hi/lo, non-persistent grid
    {
        dim3 grid(SEQ / 128, NHEAD, BATCH);
        flash_mma<<<grid, 256, FSMEM_TOTAL>>>(qh, ahi, alo);
    }

    // 3) out = attn @ Wproj (fp32 out), persistent grid
    {
        int tiles = (DIM / 128) * (M / 128);           // 256
        int grid  = tiles < NSLOTS ? tiles : NSLOTS;
        gemm_mma<false><<<grid, 256, GSMEM_TOTAL>>>(ahi, alo, wph,
                                                    out, nullptr, M, DIM, DIM);
    }
}

// round 16
// speedup vs baseline: 1.6048x; 1.2886x over previous
#include <cuda_runtime.h>
#include <cuda_fp16.h>
#include <cstdint>
#include <cstddef>

#define BATCH 2
#define SEQ   2048
#define DIM   1024
#define NHEAD 16
#define HD    64
// SCALE * log2(e): logits kept in base-2 domain (folded into Q at QKV epilogue)
#define SC2   0.18033688011112042f

#define NSLOTS 296   // 148 SMs x 2 CTAs/SM

// ---------------------------------------------------------------------------
// Scratch (allocation-free rule: __device__ globals) — pure fp16 scheme
// ---------------------------------------------------------------------------
__device__ __half g_xh [(size_t)BATCH * SEQ * DIM];       // x fp16
__device__ __half g_qh [(size_t)BATCH * SEQ * 3 * DIM];   // qkv fp16 (Q pre-scaled)
__device__ __half g_ah [(size_t)BATCH * SEQ * DIM];       // attn fp16
__device__ __half g_wqh[(size_t)3 * DIM * DIM];           // [3072,1024] K-major fp16
__device__ __half g_wph[(size_t)DIM * DIM];               // [1024,1024] K-major fp16

// ---------------------------------------------------------------------------
// Portable PTX helpers
// ---------------------------------------------------------------------------
__device__ __forceinline__ uint32_t smem_u32(const void* p) {
    uint32_t a;
    asm("{ .reg .u64 t; cvta.to.shared.u64 t, %1; cvt.u32.u64 %0, t; }" : "=r"(a) : "l"(p));
    return a;
}
#define CPA16(dst, src) \
    asm volatile("cp.async.cg.shared.global [%0], [%1], 16;" :: "r"(dst), "l"(src) : "memory")
#define CP_COMMIT() asm volatile("cp.async.commit_group;" ::: "memory")
#define CP_WAIT0()  asm volatile("cp.async.wait_group 0;" ::: "memory")
#define CP_WAIT1()  asm volatile("cp.async.wait_group 1;" ::: "memory")

#define LDSM_X4(r, addr) \
    asm volatile("ldmatrix.sync.aligned.m8n8.x4.shared.b16 {%0,%1,%2,%3}, [%4];" \
        : "=r"((r)[0]), "=r"((r)[1]), "=r"((r)[2]), "=r"((r)[3]) : "r"(addr))
#define LDSM_X4T(r, addr) \
    asm volatile("ldmatrix.sync.aligned.m8n8.x4.trans.shared.b16 {%0,%1,%2,%3}, [%4];" \
        : "=r"((r)[0]), "=r"((r)[1]), "=r"((r)[2]), "=r"((r)[3]) : "r"(addr))

// fp16 HMMA, fp32 accumulate
#define MMA16816(c, a, b) \
    asm volatile("mma.sync.aligned.m16n8k16.row.col.f32.f16.f16.f32 " \
        "{%0,%1,%2,%3}, {%4,%5,%6,%7}, {%8,%9}, {%0,%1,%2,%3};" \
        : "+f"((c)[0]), "+f"((c)[1]), "+f"((c)[2]), "+f"((c)[3]) \
        : "r"((a)[0]), "r"((a)[1]), "r"((a)[2]), "r"((a)[3]), "r"((b)[0]), "r"((b)[1]))

#define SWZ64(off)  ((off) ^ (((off) >> 3) & 0x30))
#define SWZ128(off) ((off) ^ (((off) >> 3) & 0x70))

__device__ __forceinline__ float ex2f(float x) {
    float y; asm("ex2.approx.ftz.f32 %0, %1;" : "=f"(y) : "f"(x)); return y;
}
__device__ __forceinline__ uint32_t pack_hf2(float a, float b) {
    __half2 h = __floats2half2_rn(a, b);
    return *(uint32_t*)&h;
}

// ---------------------------------------------------------------------------
// Preprocessing
// ---------------------------------------------------------------------------
__global__ __launch_bounds__(256) void quant_h(
    const float* __restrict__ X, __half* __restrict__ H, int n4)
{
    int i = blockIdx.x * blockDim.x + threadIdx.x;
    if (i >= n4) return;
    float4 v = ((const float4*)X)[i];
    __half h[4] = { __float2half_rn(v.x), __float2half_rn(v.y),
                    __float2half_rn(v.z), __float2half_rn(v.w) };
    ((uint2*)H)[i] = *(uint2*)h;
}

// W [K, N] fp32 -> T [N, K] fp16 (transpose + quantize)
__global__ __launch_bounds__(256) void transpose_h(
    const float* __restrict__ W, __half* __restrict__ Th, int K, int N)
{
    __shared__ float tile[32][33];
    int tx = threadIdx.x & 31, ty = threadIdx.x >> 5;
    int k0 = blockIdx.y * 32, n0 = blockIdx.x * 32;
    #pragma unroll
    for (int i = 0; i < 32; i += 8)
        tile[ty + i][tx] = W[(size_t)(k0 + ty + i) * N + n0 + tx];
    __syncthreads();
    #pragma unroll
    for (int i = 0; i < 32; i += 8) {
        float v = tile[tx][ty + i];
        Th[(size_t)(n0 + ty + i) * K + k0 + tx] = __float2half_rn(v);
    }
}

// ---------------------------------------------------------------------------
// HMMA fp16 GEMM (persistent CTAs): C = Ah[M,K] @ Bh[N,K]^T
// CTA tile 128x128, BK=32, 3-stage cp.async, 2 CTAs/SM, tile loop per CTA.
// Stage (16KB): A[0,8K) B[8K,16K)
// SPLIT epilogue: fp16 out, Q columns scaled by SC2; else fp32 out.
// ---------------------------------------------------------------------------
#define GST 16384
#define GSMEM_TOTAL (3 * GST)

#define LOAD_STAGE(sidx, kc) do {                                              \
    uint32_t sb = sbase + (uint32_t)(sidx) * GST;                              \
    _Pragma("unroll")                                                          \
    for (int t_ = 0; t_ < 2; ++t_) {                                           \
        int v_ = tid + t_ * 256;                                               \
        int row_ = v_ >> 2, cb_ = v_ & 3;                                      \
        uint32_t sw_ = SWZ64((uint32_t)(row_ * 64 + cb_ * 16));                \
        size_t gA_ = (size_t)(rowBase + row_) * K + (kc) + cb_ * 8;            \
        size_t gB_ = (size_t)(colBase + row_) * K + (kc) + cb_ * 8;            \
        CPA16(sb + sw_,        (const char*)(Ah + gA_));                       \
        CPA16(sb + 8192 + sw_, (const char*)(Bh + gB_));                       \
    }                                                                          \
} while (0)

template <bool SPLIT>
__global__ __launch_bounds__(256, 2) void gemm_mma(
    const __half* __restrict__ Ah, const __half* __restrict__ Bh,
    float* __restrict__ C, __half* __restrict__ Chi,
    int M, int N, int K)
{
    extern __shared__ char smem[];
    const uint32_t sbase = smem_u32(smem);
    const int tid  = threadIdx.x;
    const int lane = tid & 31;
    const int wid  = tid >> 5;
    const int wm = (wid & 3) * 32;
    const int wn = (wid >> 2) * 64;

    const int mi = lane >> 3;
    const uint32_t a_off = (uint32_t)((((mi & 1) * 8 + (lane & 7)) * 64) + (mi >> 1) * 16);
    const uint32_t b_off = (uint32_t)((((mi >> 1) * 8 + (lane & 7)) * 64) + (mi & 1) * 16);

    const int ntx = N / 128;
    const int ntiles = ntx * (M / 128);
    const int nk = K / 32;                 // 32

    for (int tIdx = blockIdx.x; tIdx < ntiles; tIdx += gridDim.x) {
        const int rowBase = (tIdx / ntx) * 128;
        const int colBase = (tIdx % ntx) * 128;

        float acc[2][8][4];
        #pragma unroll
        for (int i = 0; i < 2; i++)
            #pragma unroll
            for (int j = 0; j < 8; j++)
                #pragma unroll
                for (int q = 0; q < 4; q++) acc[i][j][q] = 0.f;

        __syncthreads();   // previous tile's smem reads complete before refill
        LOAD_STAGE(0, 0);  CP_COMMIT();
        LOAD_STAGE(1, 32); CP_COMMIT();

        int sidx = 0;
        for (int c = 0; c < nk; ++c) {
            if (c + 1 < nk) { CP_WAIT1(); } else { CP_WAIT0(); }
            __syncthreads();
            if (c + 2 < nk) {
                int ns = sidx + 2; if (ns >= 3) ns -= 3;
                LOAD_STAGE(ns, (c + 2) * 32);
                CP_COMMIT();
            }

            const uint32_t st = sbase + (uint32_t)sidx * GST;

            // hoist all A fragments for this chunk (both kb halves)
            uint32_t Af[2][2][4];
            #pragma unroll
            for (int kb2 = 0; kb2 < 2; kb2++)
                #pragma unroll
                for (int i = 0; i < 2; i++) {
                    uint32_t off = (uint32_t)((wm + i * 16) * 64 + kb2 * 32) + a_off;
                    LDSM_X4(Af[kb2][i], st + SWZ64(off));
                }

            // B fragments double-buffered across the flattened (kb, jp) loop
            uint32_t Bf[2][4];
            {
                uint32_t off = (uint32_t)(wn * 64) + b_off;   // kb=0, jp=0
                LDSM_X4(Bf[0], st + 8192 + SWZ64(off));
            }
            int bb = 0;
            #pragma unroll
            for (int it = 0; it < 8; it++) {            // it = kb*4 + jp
                const int kb = it >> 2, jp = it & 3;
                if (it + 1 < 8) {
                    const int nkb = (it + 1) >> 2, njp = (it + 1) & 3;
                    uint32_t off = (uint32_t)((wn + njp * 16) * 64 + nkb * 32) + b_off;
                    LDSM_X4(Bf[bb ^ 1], st + 8192 + SWZ64(off));
                }
                #pragma unroll
                for (int i = 0; i < 2; i++)
                    #pragma unroll
                    for (int jj = 0; jj < 2; jj++)
                        MMA16816(acc[i][jp * 2 + jj], Af[kb][i], (&Bf[bb][jj * 2]));
                bb ^= 1;
            }
            ++sidx; if (sidx >= 3) sidx = 0;
        }

        // SC2 folded into Q columns (SPLIT path only; colBase uniform per CTA)
        const float oscale = (SPLIT && colBase < DIM) ? SC2 : 1.0f;

        #pragma unroll
        for (int i = 0; i < 2; i++) {
            #pragma unroll
            for (int j = 0; j < 8; j++) {
                int r0 = rowBase + wm + i * 16 + (lane >> 2);
                int c0 = colBase + wn + j * 8 + (lane & 3) * 2;
                if (SPLIT) {
                    #pragma unroll
                    for (int hh = 0; hh < 2; hh++) {
                        float v0 = acc[i][j][hh * 2] * oscale, v1 = acc[i][j][hh * 2 + 1] * oscale;
                        size_t idx = ((size_t)(r0 + hh * 8) * N + c0) >> 1;
                        ((uint32_t*)Chi)[idx] = pack_hf2(v0, v1);
                    }
                } else {
                    *(float2*)&C[(size_t)r0 * N + c0]       = make_float2(acc[i][j][0], acc[i][j][1]);
                    *(float2*)&C[(size_t)(r0 + 8) * N + c0] = make_float2(acc[i][j][2], acc[i][j][3]);
                }
            }
        }
    }
}

// ---------------------------------------------------------------------------
// Flash attention, fp16. CTA = 128 q rows of one (b,h); 8 warps.
// QK: 1-product (Q hi, K hi). PV: 1-product (P fp16, V hi).
// 3-stage KV pipeline: stage 16KB (Khi|Vhi), 3 stages + Q 16KB = 64KB.
// Non-persistent grid (512 CTAs).
// ---------------------------------------------------------------------------
#define FST     16384
#define F_KHI   0
#define F_VHI   8192
#define FQ_OFF  (3 * FST)
#define FSMEM_TOTAL (3 * FST + 16384)

#define FLOAD_KV(sidx, c0b) do {                                               \
    uint32_t sb = sbase + (uint32_t)(sidx) * FST;                              \
    _Pragma("unroll")                                                          \
    for (int t_ = 0; t_ < 2; ++t_) {                                           \
        int v_ = tid + t_ * 256;                                               \
        int row_ = v_ >> 3, ch_ = v_ & 7;                                      \
        uint32_t sw_ = SWZ128((uint32_t)(row_ * 128 + ch_ * 16));              \
        size_t base_ = ((size_t)(bS + (c0b) + row_) * 3) * DIM + hHD + ch_ * 8;\
        CPA16(sb + F_KHI + sw_, (const char*)(qh + base_ + DIM));              \
        CPA16(sb + F_VHI + sw_, (const char*)(qh + base_ + 2 * DIM));          \
    }                                                                          \
} while (0)

__global__ __launch_bounds__(256, 2) void flash_mma(
    const __half* __restrict__ qh, __half* __restrict__ Ah)
{
    extern __shared__ char smem[];
    const uint32_t sbase = smem_u32(smem);
    const int tid  = threadIdx.x;
    const int lane = tid & 31;
    const int wid  = tid >> 5;
    const int wrow = wid * 16;
    const int h  = blockIdx.y;
    const int b  = blockIdx.z;
    const int q0 = blockIdx.x * 128;
    const int bS  = b * SEQ;
    const int hHD = h * HD;

    const int mi = lane >> 3;
    const uint32_t a_row = (mi & 1) * 8 + (lane & 7);
    const uint32_t a_ch  = (mi >> 1) * 16;
    const uint32_t b_row = (mi >> 1) * 8 + (lane & 7);
    const uint32_t b_ch  = (mi & 1) * 16;

    // Q tile + KV stages 0,1 (two commit groups in flight)
    {
        #pragma unroll
        for (int t_ = 0; t_ < 4; ++t_) {
            int v_ = tid + t_ * 256;
            int row_ = v_ >> 3, ch_ = v_ & 7;
            uint32_t sw_ = SWZ128((uint32_t)(row_ * 128 + ch_ * 16));
            size_t base_ = ((size_t)(bS + q0 + row_) * 3) * DIM + hHD + ch_ * 8;
            CPA16(sbase + FQ_OFF + sw_, (const char*)(qh + base_));
        }
        FLOAD_KV(0, 0);
        CP_COMMIT();
        FLOAD_KV(1, 64);
        CP_COMMIT();
    }

    float S[8][4];
    float O[8][4];
    #pragma unroll
    for (int j = 0; j < 8; j++)
        #pragma unroll
        for (int q = 0; q < 4; q++) O[j][q] = 0.f;
    float mA = -1e30f, mB = -1e30f, lA = 0.f, lB = 0.f;

    const int ntiles = SEQ / 64;   // 32
    int sidx = 0;                  // stage of tile tI (mod 3)

    for (int tI = 0; tI < ntiles; ++tI) {
        if (tI + 1 < ntiles) { CP_WAIT1(); } else { CP_WAIT0(); }
        __syncthreads();           // all warps done reading stage (tI+2)%3
        if (tI + 2 < ntiles) {
            int ns = sidx + 2; if (ns >= 3) ns -= 3;
            FLOAD_KV(ns, (tI + 2) * 64);
            CP_COMMIT();
        }

        const uint32_t st = sbase + (uint32_t)sidx * FST;

        // ---- S = Q K^T (1-product) ----
        #pragma unroll
        for (int nb = 0; nb < 8; nb++)
            #pragma unroll
            for (int q = 0; q < 4; q++) S[nb][q] = 0.f;

        uint32_t Kh[2][4];
        {
            uint32_t koff = SWZ128((uint32_t)(b_row * 128) + b_ch);   // dks=0, nbp=0
            LDSM_X4(Kh[0], st + F_KHI + koff);
        }
        uint32_t qf[4];
        int kb = 0;
        #pragma unroll
        for (int it = 0; it < 16; it++) {           // it = dks*4 + nbp
            const int dks = it >> 2, nbp = it & 3;
            if (nbp == 0) {
                uint32_t qoff = SWZ128((uint32_t)((wrow + a_row) * 128 + dks * 32) + a_ch);
                LDSM_X4(qf, sbase + FQ_OFF + qoff);
            }
            if (it + 1 < 16) {
                const int nd = (it + 1) >> 2, nn = (it + 1) & 3;
                uint32_t koff = SWZ128((uint32_t)((nn * 16 + b_row) * 128 + nd * 32) + b_ch);
                LDSM_X4(Kh[kb ^ 1], st + F_KHI + koff);
            }
            float* s0 = S[nbp * 2 + 0];
            float* s1 = S[nbp * 2 + 1];
            MMA16816(s0, qf, (&Kh[kb][0]));
            MMA16816(s1, qf, (&Kh[kb][2]));
            kb ^= 1;
        }

        // ---- row max + O rescale ----
        float mxA = -1e30f, mxB = -1e30f;
        #pragma unroll
        for (int nb = 0; nb < 8; nb++) {
            mxA = fmaxf(mxA, fmaxf(S[nb][0], S[nb][1]));
            mxB = fmaxf(mxB, fmaxf(S[nb][2], S[nb][3]));
        }
        #pragma unroll
        for (int d = 1; d <= 2; d <<= 1) {
            mxA = fmaxf(mxA, __shfl_xor_sync(0xffffffffu, mxA, d));
            mxB = fmaxf(mxB, __shfl_xor_sync(0xffffffffu, mxB, d));
        }
        float mAn = fmaxf(mA, mxA), mBn = fmaxf(mB, mxB);
        float fA = ex2f(mA - mAn),  fB = ex2f(mB - mBn);
        #pragma unroll
        for (int j = 0; j < 8; j++) {
            O[j][0] *= fA; O[j][1] *= fA; O[j][2] *= fB; O[j][3] *= fB;
        }

        // ---- PV (1-product: P fp16, V hi; exp interleaved) ----
        float sA = 0.f, sB = 0.f;
        uint32_t Vh[2][4];
        {
            uint32_t voff = SWZ128((uint32_t)(a_row * 128) + a_ch);   // ks=0, dg=0
            LDSM_X4T(Vh[0], st + F_VHI + voff);
        }
        uint32_t ph[4];
        int vb = 0;
        #pragma unroll
        for (int it = 0; it < 16; it++) {           // it = ks*4 + dg
            const int ks = it >> 2, dg = it & 3;
            if (dg == 0) {
                float pv[2][4];
                #pragma unroll
                for (int jj = 0; jj < 2; jj++) {
                    const float* sv = S[ks * 2 + jj];
                    pv[jj][0] = ex2f(sv[0] - mAn);
                    pv[jj][1] = ex2f(sv[1] - mAn);
                    pv[jj][2] = ex2f(sv[2] - mBn);
                    pv[jj][3] = ex2f(sv[3] - mBn);
                    sA += pv[jj][0] + pv[jj][1];
                    sB += pv[jj][2] + pv[jj][3];
                }
                #pragma unroll
                for (int u = 0; u < 4; u++) {
                    const float* sv = pv[u >> 1];
                    ph[u] = pack_hf2(sv[(u & 1) * 2], sv[(u & 1) * 2 + 1]);
                }
            }
            if (it + 1 < 16) {
                const int nks = (it + 1) >> 2, ndg = (it + 1) & 3;
                uint32_t voff = SWZ128((uint32_t)((nks * 16 + a_row) * 128 + ndg * 32) + a_ch);
                LDSM_X4T(Vh[vb ^ 1], st + F_VHI + voff);
            }
            float* o0 = O[dg * 2 + 0];
            float* o1 = O[dg * 2 + 1];
            MMA16816(o0, ph, (&Vh[vb][0]));
            MMA16816(o1, ph, (&Vh[vb][2]));
            vb ^= 1;
        }
        #pragma unroll
        for (int d = 1; d <= 2; d <<= 1) {
            sA += __shfl_xor_sync(0xffffffffu, sA, d);
            sB += __shfl_xor_sync(0xffffffffu, sB, d);
        }
        lA = lA * fA + sA;  lB = lB * fB + sB;
        mA = mAn;           mB = mBn;

        ++sidx; if (sidx >= 3) sidx = 0;
    }

    // ---- epilogue: normalize, quantize to fp16, store ----
    float invA = 1.f / lA, invB = 1.f / lB;
    int rA = bS + q0 + wrow + (lane >> 2);
    int rB = rA + 8;
    #pragma unroll
    for (int j = 0; j < 8; j++) {
        int d0 = j * 8 + (lane & 3) * 2;
        size_t iA = ((size_t)rA * DIM + hHD + d0) >> 1;
        size_t iB = ((size_t)rB * DIM + hHD + d0) >> 1;
        ((uint32_t*)Ah)[iA] = pack_hf2(O[j][0] * invA, O[j][1] * invA);
        ((uint32_t*)Ah)[iB] = pack_hf2(O[j][2] * invB, O[j][3] * invB);
    }
}

// ---------------------------------------------------------------------------
extern "C" void kernel_launch(void* const* d_in, const int* in_sizes, int n_in,
                              void* d_out, int out_size)
{
    const float* x     = (const float*)d_in[0];
    const float* Wqkv  = (const float*)d_in[1];
    const float* Wproj = (const float*)d_in[2];
    float* out = (float*)d_out;

    __half *xh, *qh, *ah, *wqh, *wph;
    cudaGetSymbolAddress((void**)&xh,  g_xh);
    cudaGetSymbolAddress((void**)&qh,  g_qh);
    cudaGetSymbolAddress((void**)&ah,  g_ah);
    cudaGetSymbolAddress((void**)&wqh, g_wqh);
    cudaGetSymbolAddress((void**)&wph, g_wph);

    const int M = BATCH * SEQ;          // 4096

    cudaFuncSetAttribute(gemm_mma<true>,  cudaFuncAttributeMaxDynamicSharedMemorySize, GSMEM_TOTAL);
    cudaFuncSetAttribute(gemm_mma<false>, cudaFuncAttributeMaxDynamicSharedMemorySize, GSMEM_TOTAL);
    cudaFuncSetAttribute(flash_mma,       cudaFuncAttributeMaxDynamicSharedMemorySize, FSMEM_TOTAL);

    // 0) quantize x / transpose+quantize weights
    quant_h<<<(M * DIM / 4 + 255) / 256, 256>>>(x, xh, M * DIM / 4);
    {
        dim3 g1(3 * DIM / 32, DIM / 32);
        transpose_h<<<g1, 256>>>(Wqkv, wqh, DIM, 3 * DIM);
        dim3 g2(DIM / 32, DIM / 32);
        transpose_h<<<g2, 256>>>(Wproj, wph, DIM, DIM);
    }

    // 1) qkv = x @ Wqkv -> fp16 (Q pre-scaled by SC2), persistent grid
    {
        int tiles = (3 * DIM / 128) * (M / 128);       // 768
        int grid  = tiles < NSLOTS ? tiles : NSLOTS;
        gemm_mma<true><<<grid, 256, GSMEM_TOTAL>>>(xh, wqh, nullptr, qh, M, 3 * DIM, DIM);
    }

    // 2) flash attention -> fp16, non-persistent grid
    {
        dim3 grid(SEQ / 128, NHEAD, BATCH);
        flash_mma<<<grid, 256, FSMEM_TOTAL>>>(qh, ah);
    }

    // 3) out = attn @ Wproj (fp32 out), persistent grid
    {
        int tiles = (DIM / 128) * (M / 128);           // 256
        int grid  = tiles < NSLOTS ? tiles : NSLOTS;
        gemm_mma<false><<<grid, 256, GSMEM_TOTAL>>>(ah, wph, out, nullptr, M, DIM, DIM);
    }
}